// round 5
// baseline (speedup 1.0000x reference)
#include <cuda_runtime.h>

#define BB    4
#define NQ    2048
#define DIMK  1024
#define HEADS 16
#define DH    64
#define INNER 1024
#define NCOLS 3072
#define SPLIT 4

#define A_ELEMS (BB*NQ*INNER)
#define M_ELEMS (BB*HEADS*DH*DH)

__device__ float g_q[BB*HEADS*NQ*DH];
__device__ float g_k[BB*HEADS*NQ*DH];
__device__ float g_v[BB*HEADS*NQ*DH];
__device__ float g_kt[BB*HEADS*NQ*DH];   // tf32-RNA bits
__device__ float g_vt[BB*HEADS*NQ*DH];   // tf32-RNA bits
__device__ float g_xt[BB*NQ*DIMK];       // tf32-RNA bits
__device__ float g_wt[DIMK*NCOLS];       // tf32-RNA bits
__device__ float g_mpart[BB*HEADS*SPLIT*DH*DH];
__device__ float g_zpart[BB*HEADS*SPLIT*DH];

__device__ __forceinline__ unsigned f2tf(float f) {
    unsigned u; asm("cvt.rna.tf32.f32 %0, %1;" : "=r"(u) : "f"(f)); return u;
}
__device__ __forceinline__ void mma8(float* c, const unsigned* a, const unsigned* b) {
    asm volatile(
        "mma.sync.aligned.m16n8k8.row.col.f32.tf32.tf32.f32 "
        "{%0,%1,%2,%3}, {%4,%5,%6,%7}, {%8,%9}, {%0,%1,%2,%3};\n"
        : "+f"(c[0]), "+f"(c[1]), "+f"(c[2]), "+f"(c[3])
        : "r"(a[0]), "r"(a[1]), "r"(a[2]), "r"(a[3]), "r"(b[0]), "r"(b[1]));
}
__device__ __forceinline__ float sigma_f(float f) {
    return (f > 0.f) ? (f + 1.f) : __expf(f);
}
__device__ __forceinline__ unsigned sptr(const void* p) {
    return (unsigned)__cvta_generic_to_shared(p);
}
#define CP16(dst, src) asm volatile("cp.async.ca.shared.global [%0], [%1], 16;" :: "r"(dst), "l"(src))
#define CP_COMMIT()    asm volatile("cp.async.commit_group;")
#define CP_WAIT0()     asm volatile("cp.async.wait_group 0;")

// ---------------------------------------------------------------------------
// Kernel 0: pre-convert x and W to tf32-RNA bits (vectorized)
// ---------------------------------------------------------------------------
__global__ __launch_bounds__(256)
void preconv(const float* __restrict__ x, const float* __restrict__ W) {
    const int nx = BB*NQ*DIMK/4;
    const int nw = DIMK*NCOLS/4;
    int i = blockIdx.x*256 + threadIdx.x;
    if (i < nx) {
        float4 v = ((const float4*)x)[i];
        uint4 u = make_uint4(f2tf(v.x), f2tf(v.y), f2tf(v.z), f2tf(v.w));
        ((uint4*)g_xt)[i] = u;
    } else if (i < nx + nw) {
        int j = i - nx;
        float4 v = ((const float4*)W)[j];
        uint4 u = make_uint4(f2tf(v.x), f2tf(v.y), f2tf(v.z), f2tf(v.w));
        ((uint4*)g_wt)[j] = u;
    }
}

// ---------------------------------------------------------------------------
// Kernel 1: QKV GEMM, cp.async 2-stage pipeline, tf32 mma
// ---------------------------------------------------------------------------
__global__ __launch_bounds__(256, 2)
void qkv_gemm(void) {
    __shared__ __align__(16) float As[2][128*20];
    __shared__ __align__(16) float Bs[2][16*136];

    const int tid  = threadIdx.x;
    const int bm   = blockIdx.y * 128, bn = blockIdx.x * 128;
    const int wid  = tid >> 5, lane = tid & 31;
    const int wm   = (wid & 1) * 64, wn = (wid >> 1) * 32;
    const int lr   = lane >> 2, lc = lane & 3;

    // cp.async mapping: A 512 chunks (row=c>>2, k4=(c&3)*4), B 512 chunks (row=c>>5, c4=(c&31)*4)
    const int arow = tid >> 2, ak4 = (tid & 3) << 2;
    const int brow = tid >> 5, bc4 = (tid & 31) << 2;
    const float* asrc0 = g_xt + (size_t)(bm + arow) * DIMK + ak4;
    const float* asrc1 = asrc0 + (size_t)64 * DIMK;
    const float* bsrc0 = g_wt + (size_t)brow * NCOLS + bn + bc4;
    const float* bsrc1 = bsrc0 + (size_t)8 * NCOLS;
    unsigned ad0[2], ad1[2], bd0[2], bd1[2];
    #pragma unroll
    for (int s = 0; s < 2; s++) {
        ad0[s] = sptr(&As[s][arow*20 + ak4]);
        ad1[s] = sptr(&As[s][(arow+64)*20 + ak4]);
        bd0[s] = sptr(&Bs[s][brow*136 + bc4]);
        bd1[s] = sptr(&Bs[s][(brow+8)*136 + bc4]);
    }

    // stage 0
    CP16(ad0[0], asrc0); CP16(ad1[0], asrc1);
    CP16(bd0[0], bsrc0); CP16(bd1[0], bsrc1);
    CP_COMMIT();

    float cacc[4][4][4];
    #pragma unroll
    for (int i = 0; i < 4; i++)
        #pragma unroll
        for (int j = 0; j < 4; j++) { cacc[i][j][0]=0.f; cacc[i][j][1]=0.f; cacc[i][j][2]=0.f; cacc[i][j][3]=0.f; }

    int cur = 0;
    for (int kt = 0; kt < DIMK/16; ++kt) {
        CP_WAIT0();
        __syncthreads();
        if (kt + 1 < DIMK/16) {
            int ko = (kt + 1) * 16;
            int nx = cur ^ 1;
            CP16(ad0[nx], asrc0 + ko);
            CP16(ad1[nx], asrc1 + ko);
            CP16(bd0[nx], bsrc0 + (size_t)ko * NCOLS);
            CP16(bd1[nx], bsrc1 + (size_t)ko * NCOLS);
            CP_COMMIT();
        }

        const unsigned* Au = (const unsigned*)As[cur];
        const unsigned* Bu = (const unsigned*)Bs[cur];
        #pragma unroll
        for (int ks = 0; ks < 2; ++ks) {
            unsigned af[4][4];
            #pragma unroll
            for (int mt = 0; mt < 4; ++mt) {
                int r = wm + mt*16 + lr, k = ks*8 + lc;
                af[mt][0] = Au[r*20 + k];
                af[mt][1] = Au[(r+8)*20 + k];
                af[mt][2] = Au[r*20 + k + 4];
                af[mt][3] = Au[(r+8)*20 + k + 4];
            }
            unsigned bf[4][2];
            #pragma unroll
            for (int nt = 0; nt < 4; ++nt) {
                int c = wn + nt*8 + lr, k = ks*8 + lc;
                bf[nt][0] = Bu[k*136 + c];
                bf[nt][1] = Bu[(k+4)*136 + c];
            }
            #pragma unroll
            for (int mt = 0; mt < 4; ++mt)
                #pragma unroll
                for (int nt = 0; nt < 4; ++nt)
                    mma8(cacc[mt][nt], af[mt], bf[nt]);
        }
        cur ^= 1;
    }

    const int part = (bn + wn) >> 10;   // bn multiple of 128 -> part uniform per CTA
    float* dst  = (part == 0) ? g_q : (part == 1) ? g_k : g_v;
    float* dst2 = (part == 1) ? g_kt : g_vt;
    #pragma unroll
    for (int mt = 0; mt < 4; ++mt) {
        int r0 = bm + wm + mt*16 + lr;
        #pragma unroll
        for (int nt = 0; nt < 4; ++nt) {
            int cg = bn + wn + nt*8 + 2*lc;
            int hh = (cg >> 6) & (HEADS - 1);
            int dd = cg & 63;
            int bi = r0 >> 11, nn = r0 & 2047;
            size_t off = (((size_t)(bi*HEADS + hh) * NQ + nn) * DH) + dd;
            *(float2*)&dst[off] = make_float2(cacc[mt][nt][0], cacc[mt][nt][1]);
            if (part) *(float2*)&dst2[off] = make_float2(
                __uint_as_float(f2tf(cacc[mt][nt][0])), __uint_as_float(f2tf(cacc[mt][nt][1])));
            int r1 = r0 + 8;
            bi = r1 >> 11; nn = r1 & 2047;
            size_t off2 = (((size_t)(bi*HEADS + hh) * NQ + nn) * DH) + dd;
            *(float2*)&dst[off2] = make_float2(cacc[mt][nt][2], cacc[mt][nt][3]);
            if (part) *(float2*)&dst2[off2] = make_float2(
                __uint_as_float(f2tf(cacc[mt][nt][2])), __uint_as_float(f2tf(cacc[mt][nt][3])));
        }
    }
}

// ---------------------------------------------------------------------------
// Kernel 2: flash attention, cp.async K/V pipeline, shuffle P conversion
// smem: Kb[2][64*68] | Vb[2][64*72] | Zs[64]
// ---------------------------------------------------------------------------
#define ATT_SMEM_WORDS (2*64*68 + 2*64*72 + 64)
#define ATT_SMEM_BYTES (ATT_SMEM_WORDS*4)
#define SCL2 0.1803368801111204f   // 0.125 * log2(e)

__global__ __launch_bounds__(256, 2)
void attn_k(const float* __restrict__ M_in, const float* __restrict__ Z_in,
            const float* __restrict__ beta_gate, float* __restrict__ outA) {
    extern __shared__ float sm[];
    float* Kb[2] = { sm, sm + 64*68 };
    float* Vb[2] = { sm + 2*64*68, sm + 2*64*68 + 64*72 };
    float* Zs = sm + 2*64*68 + 2*64*72;

    const int tid = threadIdx.x, wid = tid >> 5, lane = tid & 31;
    const int lr = lane >> 2, lc = lane & 3;
    const int b = blockIdx.z, h = blockIdx.y, bh = b*HEADS + h;
    const int qb = blockIdx.x * 128;
    const int rowA = wid*16 + lr;

    const float* qg = g_q + ((size_t)bh*NQ + qb)*DH;
    const float* ktg = g_kt + (size_t)bh*NQ*DH;
    const float* vtg = g_vt + (size_t)bh*NQ*DH;

    // cp.async mapping for K/V tiles: 1024 chunks each, 4/thread
    const int crow = tid >> 4;                 // rows crow, crow+16, crow+32, crow+48
    const int cc4  = (tid & 15) << 2;
    unsigned kdst[2][4], vdst[2][4];
    #pragma unroll
    for (int s = 0; s < 2; s++)
        #pragma unroll
        for (int t = 0; t < 4; t++) {
            kdst[s][t] = sptr(&Kb[s][(crow + 16*t)*68 + cc4]);
            vdst[s][t] = sptr(&Vb[s][(crow + 16*t)*72 + cc4]);
        }
    const float* ksrc = ktg + (size_t)crow*DH + cc4;
    const float* vsrc = vtg + (size_t)crow*DH + cc4;

    // Q fragments (RNA, one-time)
    unsigned qa[8][4];
    {
        const float* q0 = qg + (size_t)rowA*DH;
        const float* q1 = qg + (size_t)(rowA+8)*DH;
        #pragma unroll
        for (int ks = 0; ks < 8; ++ks) {
            qa[ks][0] = f2tf(q0[ks*8 + lc]);
            qa[ks][1] = f2tf(q1[ks*8 + lc]);
            qa[ks][2] = f2tf(q0[ks*8 + lc + 4]);
            qa[ks][3] = f2tf(q1[ks*8 + lc + 4]);
        }
    }

    // stage tile 0
    #pragma unroll
    for (int t = 0; t < 4; t++) {
        CP16(kdst[0][t], ksrc + (size_t)16*t*DH);
        CP16(vdst[0][t], vsrc + (size_t)16*t*DH);
    }
    CP_COMMIT();

    float oacc[8][4];
    #pragma unroll
    for (int i = 0; i < 8; i++) { oacc[i][0]=0.f; oacc[i][1]=0.f; oacc[i][2]=0.f; oacc[i][3]=0.f; }
    float m1 = -1e30f, m2 = -1e30f, l1 = 0.f, l2 = 0.f;

    const int src  = lr*4 + (lc >> 1);
    const bool hi  = lc & 1;

    int cur = 0;
    for (int jt = 0; jt < NQ; jt += 64) {
        CP_WAIT0();
        __syncthreads();
        if (jt + 64 < NQ) {
            int nx = cur ^ 1;
            const float* kn = ksrc + (size_t)(jt + 64)*DH;
            const float* vn = vsrc + (size_t)(jt + 64)*DH;
            #pragma unroll
            for (int t = 0; t < 4; t++) {
                CP16(kdst[nx][t], kn + (size_t)16*t*DH);
                CP16(vdst[nx][t], vn + (size_t)16*t*DH);
            }
            CP_COMMIT();
        }
        const unsigned* Kc = (const unsigned*)Kb[cur];
        const unsigned* Vc = (const unsigned*)Vb[cur];

        // S = Q K^T
        float sacc[8][4];
        #pragma unroll
        for (int i = 0; i < 8; i++) { sacc[i][0]=0.f; sacc[i][1]=0.f; sacc[i][2]=0.f; sacc[i][3]=0.f; }
        #pragma unroll
        for (int ks = 0; ks < 8; ++ks) {
            #pragma unroll
            for (int nt = 0; nt < 8; ++nt) {
                unsigned bf[2];
                const unsigned* kp = &Kc[(nt*8 + lr)*68 + ks*8 + lc];
                bf[0] = kp[0]; bf[1] = kp[4];
                mma8(sacc[nt], qa[ks], bf);
            }
        }

        // online softmax (base-2)
        float tmax1 = -1e30f, tmax2 = -1e30f;
        #pragma unroll
        for (int nt = 0; nt < 8; ++nt) {
            tmax1 = fmaxf(tmax1, fmaxf(sacc[nt][0], sacc[nt][1]));
            tmax2 = fmaxf(tmax2, fmaxf(sacc[nt][2], sacc[nt][3]));
        }
        tmax1 = fmaxf(tmax1, __shfl_xor_sync(0xffffffffu, tmax1, 1));
        tmax1 = fmaxf(tmax1, __shfl_xor_sync(0xffffffffu, tmax1, 2));
        tmax2 = fmaxf(tmax2, __shfl_xor_sync(0xffffffffu, tmax2, 1));
        tmax2 = fmaxf(tmax2, __shfl_xor_sync(0xffffffffu, tmax2, 2));

        float mn1 = fmaxf(m1, tmax1*SCL2), mn2 = fmaxf(m2, tmax2*SCL2);
        float corr1 = exp2f(m1 - mn1), corr2 = exp2f(m2 - mn2);
        float rs1 = 0.f, rs2 = 0.f;
        #pragma unroll
        for (int nt = 0; nt < 8; ++nt) {
            sacc[nt][0] = exp2f(sacc[nt][0]*SCL2 - mn1);
            sacc[nt][1] = exp2f(sacc[nt][1]*SCL2 - mn1);
            sacc[nt][2] = exp2f(sacc[nt][2]*SCL2 - mn2);
            sacc[nt][3] = exp2f(sacc[nt][3]*SCL2 - mn2);
            rs1 += sacc[nt][0] + sacc[nt][1];
            rs2 += sacc[nt][2] + sacc[nt][3];
        }
        rs1 += __shfl_xor_sync(0xffffffffu, rs1, 1);
        rs1 += __shfl_xor_sync(0xffffffffu, rs1, 2);
        rs2 += __shfl_xor_sync(0xffffffffu, rs2, 1);
        rs2 += __shfl_xor_sync(0xffffffffu, rs2, 2);
        l1 = l1*corr1 + rs1;
        l2 = l2*corr2 + rs2;
        #pragma unroll
        for (int nt = 0; nt < 8; ++nt) {
            oacc[nt][0] *= corr1; oacc[nt][1] *= corr1;
            oacc[nt][2] *= corr2; oacc[nt][3] *= corr2;
        }
        m1 = mn1; m2 = mn2;

        // O += P V (shuffle C-layout -> A-fragment)
        #pragma unroll
        for (int ks = 0; ks < 8; ++ks) {
            float e0 = __shfl_sync(0xffffffffu, sacc[ks][0], src);
            float e1 = __shfl_sync(0xffffffffu, sacc[ks][1], src);
            float e2 = __shfl_sync(0xffffffffu, sacc[ks][2], src);
            float e3 = __shfl_sync(0xffffffffu, sacc[ks][3], src);
            float f0 = __shfl_sync(0xffffffffu, sacc[ks][0], src + 2);
            float f1 = __shfl_sync(0xffffffffu, sacc[ks][1], src + 2);
            float f2v = __shfl_sync(0xffffffffu, sacc[ks][2], src + 2);
            float f3 = __shfl_sync(0xffffffffu, sacc[ks][3], src + 2);
            unsigned a[4];
            a[0] = f2tf(hi ? e1 : e0);
            a[1] = f2tf(hi ? e3 : e2);
            a[2] = f2tf(hi ? f1 : f0);
            a[3] = f2tf(hi ? f3 : f2v);
            #pragma unroll
            for (int nt = 0; nt < 8; ++nt) {
                unsigned bf[2];
                bf[0] = Vc[(ks*8 + lc)*72 + nt*8 + lr];
                bf[1] = Vc[(ks*8 + lc + 4)*72 + nt*8 + lr];
                mma8(oacc[nt], a, bf);
            }
        }
        cur ^= 1;
    }

    // epilogue: memory branch (sigma(Q) @ M)
    __syncthreads();
    const float* Mg = M_in + (size_t)bh*DH*DH;
    unsigned* Kb0 = (unsigned*)Kb[0];
    for (int i = tid; i < DH*DH; i += 256) {
        int d = i >> 6, v = i & 63;
        Kb0[v*68 + d] = f2tf(Mg[i]);
    }
    if (tid < DH) Zs[tid] = Z_in[bh*DH + tid];
    __syncthreads();

    float macc[8][4];
    #pragma unroll
    for (int i = 0; i < 8; i++) { macc[i][0]=0.f; macc[i][1]=0.f; macc[i][2]=0.f; macc[i][3]=0.f; }
    float den1 = 0.f, den2 = 0.f;

    #pragma unroll
    for (int ks = 0; ks < 8; ++ks) {
        unsigned a[4];
        float s0 = sigma_f(__uint_as_float(qa[ks][0]));
        float s1 = sigma_f(__uint_as_float(qa[ks][1]));
        float s2 = sigma_f(__uint_as_float(qa[ks][2]));
        float s3 = sigma_f(__uint_as_float(qa[ks][3]));
        a[0] = f2tf(s0); a[1] = f2tf(s1); a[2] = f2tf(s2); a[3] = f2tf(s3);
        den1 += s0*Zs[ks*8+lc] + s2*Zs[ks*8+lc+4];
        den2 += s1*Zs[ks*8+lc] + s3*Zs[ks*8+lc+4];
        #pragma unroll
        for (int nt = 0; nt < 8; ++nt) {
            unsigned bf[2];
            const unsigned* mp = &Kb0[(nt*8 + lr)*68 + ks*8 + lc];
            bf[0] = mp[0]; bf[1] = mp[4];
            mma8(macc[nt], a, bf);
        }
    }
    den1 += __shfl_xor_sync(0xffffffffu, den1, 1);
    den1 += __shfl_xor_sync(0xffffffffu, den1, 2);
    den2 += __shfl_xor_sync(0xffffffffu, den2, 1);
    den2 += __shfl_xor_sync(0xffffffffu, den2, 2);

    float g = 1.f / (1.f + __expf(-beta_gate[h]));
    float iv1 = 1.f/l1, iv2 = 1.f/l2, id1 = 1.f/den1, id2 = 1.f/den2;

    int n1 = qb + rowA;
    float* o1 = outA + ((size_t)(b*NQ + n1))*INNER + h*DH;
    float* o2 = o1 + (size_t)8*INNER;
    #pragma unroll
    for (int nt = 0; nt < 8; ++nt) {
        int d = nt*8 + 2*lc;
        *(float2*)&o1[d] = make_float2(
            g*macc[nt][0]*id1 + (1.f-g)*oacc[nt][0]*iv1,
            g*macc[nt][1]*id1 + (1.f-g)*oacc[nt][1]*iv1);
        *(float2*)&o2[d] = make_float2(
            g*macc[nt][2]*id2 + (1.f-g)*oacc[nt][2]*iv2,
            g*macc[nt][3]*id2 + (1.f-g)*oacc[nt][3]*iv2);
    }
}

// ---------------------------------------------------------------------------
// Kernel 3a: state partials, split over n
// ---------------------------------------------------------------------------
#define CN 32
__global__ __launch_bounds__(256)
void state_part(const float* __restrict__ M_in, const float* __restrict__ Z_in) {
    __shared__ float Ms[DH][DH];
    __shared__ float Zs[DH];
    __shared__ float sks[CN][DH];
    __shared__ float dvs[CN][DH];
    __shared__ float invden[CN];

    const int tid = threadIdx.x;
    const int bh = blockIdx.x >> 2;
    const int chunk = blockIdx.x & 3;
    const int nrows = NQ / SPLIT;

    const float* Mg = M_in + (size_t)bh * DH * DH;
    for (int e = tid; e < DH*DH; e += 256) Ms[e >> 6][e & 63] = Mg[e];
    if (tid < DH) Zs[tid] = Z_in[bh*DH + tid];

    const float* kg = g_k + (size_t)bh*NQ*DH + (size_t)chunk*nrows*DH;
    const float* vg = g_v + (size_t)bh*NQ*DH + (size_t)chunk*nrows*DH;

    const int dgrp = tid >> 2;
    const int vb   = (tid & 3) << 4;
    float macc[16];
    #pragma unroll
    for (int i = 0; i < 16; i++) macc[i] = 0.f;
    float zacc = 0.f;

    for (int n0 = 0; n0 < nrows; n0 += CN) {
        __syncthreads();
        #pragma unroll
        for (int i = 0; i < 2; i++) {
            int fidx = tid + 256*i;
            int n = fidx >> 4, dd = (fidx & 15) << 2;
            float4 kv = *(const float4*)&kg[(size_t)(n0+n)*DH + dd];
            kv.x = sigma_f(kv.x); kv.y = sigma_f(kv.y);
            kv.z = sigma_f(kv.z); kv.w = sigma_f(kv.w);
            *(float4*)&sks[n][dd] = kv;
            *(float4*)&dvs[n][dd] = *(const float4*)&vg[(size_t)(n0+n)*DH + dd];
        }
        __syncthreads();
        if (tid < CN) {
            float acc = 0.f;
            #pragma unroll
            for (int d = 0; d < DH; d++) acc += sks[tid][d]*Zs[d];
            invden[tid] = 1.f / acc;
        }
        __syncthreads();
        #pragma unroll
        for (int e = 0; e < 8; e++) {
            int idx = tid + 256*e;
            int n = idx >> 6, v = idx & 63;
            float acc = 0.f;
            #pragma unroll
            for (int d = 0; d < DH; d++) acc += sks[n][d]*Ms[d][v];
            dvs[n][v] -= acc * invden[n];
        }
        __syncthreads();
        #pragma unroll 4
        for (int n = 0; n < CN; n++) {
            float skdn = sks[n][dgrp];
            const float* dv = &dvs[n][vb];
            #pragma unroll
            for (int vv = 0; vv < 16; vv++) macc[vv] += skdn * dv[vv];
        }
        if (tid < DH) {
            #pragma unroll
            for (int n = 0; n < CN; n++) zacc += sks[n][tid];
        }
    }

    float* mp = g_mpart + (size_t)blockIdx.x * DH*DH;
    #pragma unroll
    for (int vv = 0; vv < 16; vv++)
        mp[dgrp*DH + vb + vv] = macc[vv];
    if (tid < DH)
        g_zpart[blockIdx.x*DH + tid] = zacc;
}

// ---------------------------------------------------------------------------
// Kernel 3b: reduce partials -> out
// ---------------------------------------------------------------------------
__global__ __launch_bounds__(256)
void state_reduce(const float* __restrict__ M_in, const float* __restrict__ Z_in,
                  const float* __restrict__ beta_lin, float* __restrict__ out) {
    const int bh = blockIdx.x;
    const int tid = threadIdx.x;
    float beta = 1.f / (1.f + __expf(-beta_lin[0]));
    beta = fminf(fmaxf(beta, 0.9f), 0.999f);

    const float* p0 = g_mpart + (size_t)(bh*4 + 0)*DH*DH;
    const float* p1 = g_mpart + (size_t)(bh*4 + 1)*DH*DH;
    const float* p2 = g_mpart + (size_t)(bh*4 + 2)*DH*DH;
    const float* p3 = g_mpart + (size_t)(bh*4 + 3)*DH*DH;
    const float* Mg = M_in + (size_t)bh*DH*DH;
    float* mo = out + A_ELEMS + (size_t)bh*DH*DH;
    for (int e = tid; e < DH*DH; e += 256)
        mo[e] = beta*Mg[e] + p0[e] + p1[e] + p2[e] + p3[e];
    if (tid < DH) {
        float z = g_zpart[(bh*4+0)*DH + tid] + g_zpart[(bh*4+1)*DH + tid]
                + g_zpart[(bh*4+2)*DH + tid] + g_zpart[(bh*4+3)*DH + tid];
        out[A_ELEMS + M_ELEMS + bh*DH + tid] = beta*Z_in[bh*DH + tid] + z;
    }
}

// ---------------------------------------------------------------------------
extern "C" void kernel_launch(void* const* d_in, const int* in_sizes, int n_in,
                              void* d_out, int out_size) {
    const float* x         = (const float*)d_in[0];
    const float* M         = (const float*)d_in[1];
    const float* Z         = (const float*)d_in[2];
    const float* W         = (const float*)d_in[3];
    const float* beta_lin  = (const float*)d_in[4];
    const float* beta_gate = (const float*)d_in[5];
    float* out = (float*)d_out;

    cudaFuncSetAttribute(attn_k, cudaFuncAttributeMaxDynamicSharedMemorySize, ATT_SMEM_BYTES);

    const int npc = (BB*NQ*DIMK + DIMK*NCOLS)/4;
    preconv<<<(npc + 255)/256, 256>>>(x, W);
    qkv_gemm<<<dim3(NCOLS/128, (BB*NQ)/128), 256>>>();
    attn_k<<<dim3(NQ/128, HEADS, BB), 256, ATT_SMEM_BYTES>>>(M, Z, beta_gate, out);
    state_part<<<BB*HEADS*SPLIT, 256>>>(M, Z);
    state_reduce<<<BB*HEADS, 256>>>(M, Z, beta_lin, out);
}

// round 6
// speedup vs baseline: 1.2694x; 1.2694x over previous
#include <cuda_runtime.h>

#define BB    4
#define NQ    2048
#define DIMK  1024
#define HEADS 16
#define DH    64
#define INNER 1024
#define NCOLS 3072
#define SPLIT 4

#define A_ELEMS (BB*NQ*INNER)
#define M_ELEMS (BB*HEADS*DH*DH)

__device__ float g_q[BB*HEADS*NQ*DH];
__device__ float g_k[BB*HEADS*NQ*DH];
__device__ float g_v[BB*HEADS*NQ*DH];
__device__ float g_kt[BB*HEADS*NQ*DH];
__device__ float g_vt[BB*HEADS*NQ*DH];
__device__ float g_xt[BB*NQ*DIMK];
__device__ float g_wt[DIMK*NCOLS];
__device__ float g_mpart[BB*HEADS*SPLIT*DH*DH];
__device__ float g_zpart[BB*HEADS*SPLIT*DH];

__device__ __forceinline__ unsigned f2tf(float f) {
    unsigned u; asm("cvt.rna.tf32.f32 %0, %1;" : "=r"(u) : "f"(f)); return u;
}
__device__ __forceinline__ void mma8(float* c, const unsigned* a, const unsigned* b) {
    asm volatile(
        "mma.sync.aligned.m16n8k8.row.col.f32.tf32.tf32.f32 "
        "{%0,%1,%2,%3}, {%4,%5,%6,%7}, {%8,%9}, {%0,%1,%2,%3};\n"
        : "+f"(c[0]), "+f"(c[1]), "+f"(c[2]), "+f"(c[3])
        : "r"(a[0]), "r"(a[1]), "r"(a[2]), "r"(a[3]), "r"(b[0]), "r"(b[1]));
}
__device__ __forceinline__ float sigma_f(float f) {
    return (f > 0.f) ? (f + 1.f) : __expf(f);
}
__device__ __forceinline__ unsigned sptr(const void* p) {
    return (unsigned)__cvta_generic_to_shared(p);
}
#define CP16(dst, src) asm volatile("cp.async.ca.shared.global [%0], [%1], 16;" :: "r"(dst), "l"(src))
#define CP_COMMIT()    asm volatile("cp.async.commit_group;")
#define CP_WAIT0()     asm volatile("cp.async.wait_group 0;")

// ---------------------------------------------------------------------------
// Kernel 0: pre-convert x and W to tf32-RNA bits
// ---------------------------------------------------------------------------
__global__ __launch_bounds__(256)
void preconv(const float* __restrict__ x, const float* __restrict__ W) {
    const int nx = BB*NQ*DIMK/4;
    const int nw = DIMK*NCOLS/4;
    int i = blockIdx.x*256 + threadIdx.x;
    if (i < nx) {
        float4 v = ((const float4*)x)[i];
        ((uint4*)g_xt)[i] = make_uint4(f2tf(v.x), f2tf(v.y), f2tf(v.z), f2tf(v.w));
    } else if (i < nx + nw) {
        int j = i - nx;
        float4 v = ((const float4*)W)[j];
        ((uint4*)g_wt)[j] = make_uint4(f2tf(v.x), f2tf(v.y), f2tf(v.z), f2tf(v.w));
    }
}

// ---------------------------------------------------------------------------
// Kernel 1: QKV GEMM, cp.async 2-stage pipeline, tf32 mma
// ---------------------------------------------------------------------------
__global__ __launch_bounds__(256, 2)
void qkv_gemm(void) {
    __shared__ __align__(16) float As[2][128*20];
    __shared__ __align__(16) float Bs[2][16*136];

    const int tid  = threadIdx.x;
    const int bm   = blockIdx.y * 128, bn = blockIdx.x * 128;
    const int wid  = tid >> 5, lane = tid & 31;
    const int wm   = (wid & 1) * 64, wn = (wid >> 1) * 32;
    const int lr   = lane >> 2, lc = lane & 3;

    const int arow = tid >> 2, ak4 = (tid & 3) << 2;
    const int brow = tid >> 5, bc4 = (tid & 31) << 2;
    const float* asrc0 = g_xt + (size_t)(bm + arow) * DIMK + ak4;
    const float* asrc1 = asrc0 + (size_t)64 * DIMK;
    const float* bsrc0 = g_wt + (size_t)brow * NCOLS + bn + bc4;
    const float* bsrc1 = bsrc0 + (size_t)8 * NCOLS;
    const unsigned a_off = sptr(&As[0][arow*20 + ak4]);
    const unsigned b_off = sptr(&Bs[0][brow*136 + bc4]);
    #define ASTG (128*20*4)
    #define BSTG (16*136*4)

    CP16(a_off, asrc0); CP16(a_off + 64*20*4, asrc1);
    CP16(b_off, bsrc0); CP16(b_off + 8*136*4, bsrc1);
    CP_COMMIT();

    float cacc[4][4][4];
    #pragma unroll
    for (int i = 0; i < 4; i++)
        #pragma unroll
        for (int j = 0; j < 4; j++) { cacc[i][j][0]=0.f; cacc[i][j][1]=0.f; cacc[i][j][2]=0.f; cacc[i][j][3]=0.f; }

    int cur = 0;
    for (int kt = 0; kt < DIMK/16; ++kt) {
        CP_WAIT0();
        __syncthreads();
        if (kt + 1 < DIMK/16) {
            int ko = (kt + 1) * 16;
            unsigned ao = a_off + (cur ^ 1)*ASTG;
            unsigned bo = b_off + (cur ^ 1)*BSTG;
            CP16(ao, asrc0 + ko);
            CP16(ao + 64*20*4, asrc1 + ko);
            CP16(bo, bsrc0 + (size_t)ko * NCOLS);
            CP16(bo + 8*136*4, bsrc1 + (size_t)ko * NCOLS);
            CP_COMMIT();
        }

        const unsigned* Au = (const unsigned*)As[cur];
        const unsigned* Bu = (const unsigned*)Bs[cur];
        #pragma unroll
        for (int ks = 0; ks < 2; ++ks) {
            unsigned af[4][4];
            #pragma unroll
            for (int mt = 0; mt < 4; ++mt) {
                int r = wm + mt*16 + lr, k = ks*8 + lc;
                af[mt][0] = Au[r*20 + k];
                af[mt][1] = Au[(r+8)*20 + k];
                af[mt][2] = Au[r*20 + k + 4];
                af[mt][3] = Au[(r+8)*20 + k + 4];
            }
            unsigned bf[4][2];
            #pragma unroll
            for (int nt = 0; nt < 4; ++nt) {
                int c = wn + nt*8 + lr, k = ks*8 + lc;
                bf[nt][0] = Bu[k*136 + c];
                bf[nt][1] = Bu[(k+4)*136 + c];
            }
            #pragma unroll
            for (int mt = 0; mt < 4; ++mt)
                #pragma unroll
                for (int nt = 0; nt < 4; ++nt)
                    mma8(cacc[mt][nt], af[mt], bf[nt]);
        }
        cur ^= 1;
    }

    const int part = (bn + wn) >> 10;
    float* dst  = (part == 0) ? g_q : (part == 1) ? g_k : g_v;
    float* dst2 = (part == 1) ? g_kt : g_vt;
    #pragma unroll
    for (int mt = 0; mt < 4; ++mt) {
        int r0 = bm + wm + mt*16 + lr;
        #pragma unroll
        for (int nt = 0; nt < 4; ++nt) {
            int cg = bn + wn + nt*8 + 2*lc;
            int hh = (cg >> 6) & (HEADS - 1);
            int dd = cg & 63;
            int bi = r0 >> 11, nn = r0 & 2047;
            size_t off = (((size_t)(bi*HEADS + hh) * NQ + nn) * DH) + dd;
            *(float2*)&dst[off] = make_float2(cacc[mt][nt][0], cacc[mt][nt][1]);
            if (part) *(float2*)&dst2[off] = make_float2(
                __uint_as_float(f2tf(cacc[mt][nt][0])), __uint_as_float(f2tf(cacc[mt][nt][1])));
            int r1 = r0 + 8;
            bi = r1 >> 11; nn = r1 & 2047;
            size_t off2 = (((size_t)(bi*HEADS + hh) * NQ + nn) * DH) + dd;
            *(float2*)&dst[off2] = make_float2(cacc[mt][nt][2], cacc[mt][nt][3]);
            if (part) *(float2*)&dst2[off2] = make_float2(
                __uint_as_float(f2tf(cacc[mt][nt][2])), __uint_as_float(f2tf(cacc[mt][nt][3])));
        }
    }
}

// ---------------------------------------------------------------------------
// Kernel 2: flash attention (cp.async K/V pipeline, shuffle P conversion)
// smem: Kb[2][64*68] | Vb[2][64*72] | Zs[64]
// ---------------------------------------------------------------------------
#define ATT_SMEM_WORDS (2*64*68 + 2*64*72 + 64)
#define ATT_SMEM_BYTES (ATT_SMEM_WORDS*4)
#define SCL2 0.1803368801111204f
#define KSTG (64*68*4)
#define VSTG (64*72*4)
#define VBASE (2*KSTG)

__global__ __launch_bounds__(256, 2)
void attn_k(const float* __restrict__ M_in, const float* __restrict__ Z_in,
            const float* __restrict__ beta_gate, float* __restrict__ outA) {
    extern __shared__ float sm[];
    float* Zs = sm + 2*64*68 + 2*64*72;

    const int tid = threadIdx.x, wid = tid >> 5, lane = tid & 31;
    const int lr = lane >> 2, lc = lane & 3;
    const int b = blockIdx.z, h = blockIdx.y, bh = b*HEADS + h;
    const int qb = blockIdx.x * 128;
    const int rowA = wid*16 + lr;

    const float* qg = g_q + ((size_t)bh*NQ + qb)*DH;
    const float* ktg = g_kt + (size_t)bh*NQ*DH;
    const float* vtg = g_vt + (size_t)bh*NQ*DH;

    const int crow = tid >> 4;
    const int cc4  = (tid & 15) << 2;
    const unsigned smb = sptr(sm);
    const unsigned koff = smb + (unsigned)(crow*68 + cc4)*4;
    const unsigned voff = smb + VBASE + (unsigned)(crow*72 + cc4)*4;
    const float* ksrc = ktg + (size_t)crow*DH + cc4;
    const float* vsrc = vtg + (size_t)crow*DH + cc4;

    unsigned qa[8][4];
    {
        const float* q0 = qg + (size_t)rowA*DH;
        const float* q1 = qg + (size_t)(rowA+8)*DH;
        #pragma unroll
        for (int ks = 0; ks < 8; ++ks) {
            qa[ks][0] = f2tf(q0[ks*8 + lc]);
            qa[ks][1] = f2tf(q1[ks*8 + lc]);
            qa[ks][2] = f2tf(q0[ks*8 + lc + 4]);
            qa[ks][3] = f2tf(q1[ks*8 + lc + 4]);
        }
    }

    #pragma unroll
    for (int t = 0; t < 4; t++) {
        CP16(koff + t*(16*68*4), ksrc + (size_t)16*t*DH);
        CP16(voff + t*(16*72*4), vsrc + (size_t)16*t*DH);
    }
    CP_COMMIT();

    float oacc[8][4];
    #pragma unroll
    for (int i = 0; i < 8; i++) { oacc[i][0]=0.f; oacc[i][1]=0.f; oacc[i][2]=0.f; oacc[i][3]=0.f; }
    float m1 = -1e30f, m2 = -1e30f, l1 = 0.f, l2 = 0.f;

    const int src  = lr*4 + (lc >> 1);
    const bool hi  = lc & 1;

    int cur = 0;
    for (int jt = 0; jt < NQ; jt += 64) {
        CP_WAIT0();
        __syncthreads();
        if (jt + 64 < NQ) {
            int nx = cur ^ 1;
            const float* kn = ksrc + (size_t)(jt + 64)*DH;
            const float* vn = vsrc + (size_t)(jt + 64)*DH;
            #pragma unroll
            for (int t = 0; t < 4; t++) {
                CP16(koff + nx*KSTG + t*(16*68*4), kn + (size_t)16*t*DH);
                CP16(voff + nx*VSTG + t*(16*72*4), vn + (size_t)16*t*DH);
            }
            CP_COMMIT();
        }
        const unsigned* Kc = (const unsigned*)(sm + cur*(64*68));
        const unsigned* Vc = (const unsigned*)(sm + 2*64*68 + cur*(64*72));

        float sacc[8][4];
        #pragma unroll
        for (int i = 0; i < 8; i++) { sacc[i][0]=0.f; sacc[i][1]=0.f; sacc[i][2]=0.f; sacc[i][3]=0.f; }
        #pragma unroll
        for (int ks = 0; ks < 8; ++ks) {
            #pragma unroll
            for (int nt = 0; nt < 8; ++nt) {
                unsigned bf[2];
                const unsigned* kp = &Kc[(nt*8 + lr)*68 + ks*8 + lc];
                bf[0] = kp[0]; bf[1] = kp[4];
                mma8(sacc[nt], qa[ks], bf);
            }
        }

        float tmax1 = -1e30f, tmax2 = -1e30f;
        #pragma unroll
        for (int nt = 0; nt < 8; ++nt) {
            tmax1 = fmaxf(tmax1, fmaxf(sacc[nt][0], sacc[nt][1]));
            tmax2 = fmaxf(tmax2, fmaxf(sacc[nt][2], sacc[nt][3]));
        }
        tmax1 = fmaxf(tmax1, __shfl_xor_sync(0xffffffffu, tmax1, 1));
        tmax1 = fmaxf(tmax1, __shfl_xor_sync(0xffffffffu, tmax1, 2));
        tmax2 = fmaxf(tmax2, __shfl_xor_sync(0xffffffffu, tmax2, 1));
        tmax2 = fmaxf(tmax2, __shfl_xor_sync(0xffffffffu, tmax2, 2));

        float mn1 = fmaxf(m1, tmax1*SCL2), mn2 = fmaxf(m2, tmax2*SCL2);
        float corr1 = exp2f(m1 - mn1), corr2 = exp2f(m2 - mn2);
        float rs1 = 0.f, rs2 = 0.f;
        #pragma unroll
        for (int nt = 0; nt < 8; ++nt) {
            sacc[nt][0] = exp2f(sacc[nt][0]*SCL2 - mn1);
            sacc[nt][1] = exp2f(sacc[nt][1]*SCL2 - mn1);
            sacc[nt][2] = exp2f(sacc[nt][2]*SCL2 - mn2);
            sacc[nt][3] = exp2f(sacc[nt][3]*SCL2 - mn2);
            rs1 += sacc[nt][0] + sacc[nt][1];
            rs2 += sacc[nt][2] + sacc[nt][3];
        }
        rs1 += __shfl_xor_sync(0xffffffffu, rs1, 1);
        rs1 += __shfl_xor_sync(0xffffffffu, rs1, 2);
        rs2 += __shfl_xor_sync(0xffffffffu, rs2, 1);
        rs2 += __shfl_xor_sync(0xffffffffu, rs2, 2);
        l1 = l1*corr1 + rs1;
        l2 = l2*corr2 + rs2;
        #pragma unroll
        for (int nt = 0; nt < 8; ++nt) {
            oacc[nt][0] *= corr1; oacc[nt][1] *= corr1;
            oacc[nt][2] *= corr2; oacc[nt][3] *= corr2;
        }
        m1 = mn1; m2 = mn2;

        #pragma unroll
        for (int ks = 0; ks < 8; ++ks) {
            float e0 = __shfl_sync(0xffffffffu, sacc[ks][0], src);
            float e1 = __shfl_sync(0xffffffffu, sacc[ks][1], src);
            float e2 = __shfl_sync(0xffffffffu, sacc[ks][2], src);
            float e3 = __shfl_sync(0xffffffffu, sacc[ks][3], src);
            float f0 = __shfl_sync(0xffffffffu, sacc[ks][0], src + 2);
            float f1 = __shfl_sync(0xffffffffu, sacc[ks][1], src + 2);
            float f2v = __shfl_sync(0xffffffffu, sacc[ks][2], src + 2);
            float f3 = __shfl_sync(0xffffffffu, sacc[ks][3], src + 2);
            unsigned a[4];
            a[0] = f2tf(hi ? e1 : e0);
            a[1] = f2tf(hi ? e3 : e2);
            a[2] = f2tf(hi ? f1 : f0);
            a[3] = f2tf(hi ? f3 : f2v);
            #pragma unroll
            for (int nt = 0; nt < 8; ++nt) {
                unsigned bf[2];
                bf[0] = Vc[(ks*8 + lc)*72 + nt*8 + lr];
                bf[1] = Vc[(ks*8 + lc + 4)*72 + nt*8 + lr];
                mma8(oacc[nt], a, bf);
            }
        }
        cur ^= 1;
    }

    __syncthreads();
    const float* Mg = M_in + (size_t)bh*DH*DH;
    unsigned* Kb0 = (unsigned*)sm;
    for (int i = tid; i < DH*DH; i += 256) {
        int d = i >> 6, v = i & 63;
        Kb0[v*68 + d] = f2tf(Mg[i]);
    }
    if (tid < DH) Zs[tid] = Z_in[bh*DH + tid];
    __syncthreads();

    float macc[8][4];
    #pragma unroll
    for (int i = 0; i < 8; i++) { macc[i][0]=0.f; macc[i][1]=0.f; macc[i][2]=0.f; macc[i][3]=0.f; }
    float den1 = 0.f, den2 = 0.f;

    #pragma unroll
    for (int ks = 0; ks < 8; ++ks) {
        unsigned a[4];
        float s0 = sigma_f(__uint_as_float(qa[ks][0]));
        float s1 = sigma_f(__uint_as_float(qa[ks][1]));
        float s2 = sigma_f(__uint_as_float(qa[ks][2]));
        float s3 = sigma_f(__uint_as_float(qa[ks][3]));
        a[0] = f2tf(s0); a[1] = f2tf(s1); a[2] = f2tf(s2); a[3] = f2tf(s3);
        den1 += s0*Zs[ks*8+lc] + s2*Zs[ks*8+lc+4];
        den2 += s1*Zs[ks*8+lc] + s3*Zs[ks*8+lc+4];
        #pragma unroll
        for (int nt = 0; nt < 8; ++nt) {
            unsigned bf[2];
            const unsigned* mp = &Kb0[(nt*8 + lr)*68 + ks*8 + lc];
            bf[0] = mp[0]; bf[1] = mp[4];
            mma8(macc[nt], a, bf);
        }
    }
    den1 += __shfl_xor_sync(0xffffffffu, den1, 1);
    den1 += __shfl_xor_sync(0xffffffffu, den1, 2);
    den2 += __shfl_xor_sync(0xffffffffu, den2, 1);
    den2 += __shfl_xor_sync(0xffffffffu, den2, 2);

    float g = 1.f / (1.f + __expf(-beta_gate[h]));
    float iv1 = 1.f/l1, iv2 = 1.f/l2, id1 = 1.f/den1, id2 = 1.f/den2;

    int n1 = qb + rowA;
    float* o1 = outA + ((size_t)(b*NQ + n1))*INNER + h*DH;
    float* o2 = o1 + (size_t)8*INNER;
    #pragma unroll
    for (int nt = 0; nt < 8; ++nt) {
        int d = nt*8 + 2*lc;
        *(float2*)&o1[d] = make_float2(
            g*macc[nt][0]*id1 + (1.f-g)*oacc[nt][0]*iv1,
            g*macc[nt][1]*id1 + (1.f-g)*oacc[nt][1]*iv1);
        *(float2*)&o2[d] = make_float2(
            g*macc[nt][2]*id2 + (1.f-g)*oacc[nt][2]*iv2,
            g*macc[nt][3]*id2 + (1.f-g)*oacc[nt][3]*iv2);
    }
}

// ---------------------------------------------------------------------------
// Kernel 3a: state partials via tf32 mma.
// Per chunk of 64 rows: P = sigma(K)@M (mma), dv = V - P*invden,
// Macc += sigma(K)^T @ dv (mma). Dynamic smem:
// Sks[64*68] u32 | Vs[64*68] f32 | DVt[64*68] u32 | Mt[64*68] u32 | Zs[64] | invden[64]
// ---------------------------------------------------------------------------
#define ST_SMEM_WORDS (4*64*68 + 128)
#define ST_SMEM_BYTES (ST_SMEM_WORDS*4)

__global__ __launch_bounds__(256)
void state_part(const float* __restrict__ M_in, const float* __restrict__ Z_in) {
    extern __shared__ float ssm[];
    unsigned* Sks = (unsigned*)ssm;            // [n][d] tf32 bits of sigma(k)
    float*    Vs  = ssm + 64*68;               // [n][v] fp32
    unsigned* DVt = (unsigned*)(ssm + 2*64*68);// [v][n] tf32 bits
    unsigned* Mt  = (unsigned*)(ssm + 3*64*68);// [v][d] tf32 bits (M transposed)
    float*    Zs  = ssm + 4*64*68;
    float*    invden = Zs + 64;

    const int tid = threadIdx.x, wid = tid >> 5, lane = tid & 31;
    const int lr = lane >> 2, lc = lane & 3;
    const int bh = blockIdx.x >> 2;
    const int chunk = blockIdx.x & 3;
    const int nrows = NQ / SPLIT;
    const int rt = wid & 3, ct = wid >> 2;     // warp tile: rows rt*16, cols ct*32

    const float* Mg = M_in + (size_t)bh*DH*DH;
    for (int i = tid; i < DH*DH; i += 256) {
        int d = i >> 6, v = i & 63;
        Mt[v*68 + d] = f2tf(Mg[i]);
    }
    if (tid < DH) Zs[tid] = Z_in[bh*DH + tid];

    const float* kg = g_k + ((size_t)bh*NQ + (size_t)chunk*nrows)*DH;
    const float* vg = g_v + ((size_t)bh*NQ + (size_t)chunk*nrows)*DH;

    float macc[4][4];
    #pragma unroll
    for (int i = 0; i < 4; i++) { macc[i][0]=0.f; macc[i][1]=0.f; macc[i][2]=0.f; macc[i][3]=0.f; }
    float zpart = 0.f;                          // d = wid*8+lr, n-seg = lc*16..+15
    const int dz = wid*8 + lr;

    for (int n0 = 0; n0 < nrows; n0 += 64) {
        __syncthreads();
        #pragma unroll
        for (int t = 0; t < 4; ++t) {
            int idx = tid + 256*t;
            int r = idx >> 4, c4 = (idx & 15) << 2;
            float4 kv = *(const float4*)&kg[(size_t)(n0+r)*DH + c4];
            kv.x = sigma_f(kv.x); kv.y = sigma_f(kv.y);
            kv.z = sigma_f(kv.z); kv.w = sigma_f(kv.w);
            *(uint4*)&Sks[r*68 + c4] = make_uint4(f2tf(kv.x), f2tf(kv.y), f2tf(kv.z), f2tf(kv.w));
            *(float4*)&Vs[r*68 + c4] = *(const float4*)&vg[(size_t)(n0+r)*DH + c4];
        }
        __syncthreads();

        // den per row (8 rows per warp) + zpart accumulation
        {
            int rn = wid*8 + lr;
            float acc = 0.f;
            #pragma unroll
            for (int j = 0; j < 16; ++j) {
                int d = lc*16 + j;
                acc += __uint_as_float(Sks[rn*68 + d]) * Zs[d];
            }
            acc += __shfl_xor_sync(0xffffffffu, acc, 1);
            acc += __shfl_xor_sync(0xffffffffu, acc, 2);
            if (lc == 0) invden[rn] = 1.f / acc;
            #pragma unroll
            for (int j = 0; j < 16; ++j)
                zpart += __uint_as_float(Sks[(lc*16 + j)*68 + dz]);
        }
        __syncthreads();

        // P = Sk @ M  (C[n][v]); warp tile 16x32
        float pacc[4][4];
        #pragma unroll
        for (int i = 0; i < 4; i++) { pacc[i][0]=0.f; pacc[i][1]=0.f; pacc[i][2]=0.f; pacc[i][3]=0.f; }
        #pragma unroll
        for (int ks = 0; ks < 8; ++ks) {
            unsigned a[4];
            a[0] = Sks[(rt*16+lr)*68 + ks*8+lc];
            a[1] = Sks[(rt*16+lr+8)*68 + ks*8+lc];
            a[2] = Sks[(rt*16+lr)*68 + ks*8+lc+4];
            a[3] = Sks[(rt*16+lr+8)*68 + ks*8+lc+4];
            #pragma unroll
            for (int nt = 0; nt < 4; ++nt) {
                unsigned bf[2];
                bf[0] = Mt[(ct*32+nt*8+lr)*68 + ks*8+lc];
                bf[1] = Mt[(ct*32+nt*8+lr)*68 + ks*8+lc+4];
                mma8(pacc[nt], a, bf);
            }
        }

        // dv = V - P*invden, store transposed tf32
        {
            int r0 = rt*16 + lr, r1 = r0 + 8;
            float iv0 = invden[r0], iv1 = invden[r1];
            #pragma unroll
            for (int nt = 0; nt < 4; ++nt) {
                int c0 = ct*32 + nt*8 + 2*lc, c1 = c0 + 1;
                DVt[c0*68 + r0] = f2tf(Vs[r0*68 + c0] - pacc[nt][0]*iv0);
                DVt[c1*68 + r0] = f2tf(Vs[r0*68 + c1] - pacc[nt][1]*iv0);
                DVt[c0*68 + r1] = f2tf(Vs[r1*68 + c0] - pacc[nt][2]*iv1);
                DVt[c1*68 + r1] = f2tf(Vs[r1*68 + c1] - pacc[nt][3]*iv1);
            }
        }
        __syncthreads();

        // Macc[d][v] += Sk^T @ dv ; A[d][n] = Sks[n][d], B[v][n] = DVt
        #pragma unroll
        for (int ks = 0; ks < 8; ++ks) {
            unsigned a[4];
            a[0] = Sks[(ks*8+lc)*68 + rt*16+lr];
            a[1] = Sks[(ks*8+lc)*68 + rt*16+lr+8];
            a[2] = Sks[(ks*8+lc+4)*68 + rt*16+lr];
            a[3] = Sks[(ks*8+lc+4)*68 + rt*16+lr+8];
            #pragma unroll
            for (int nt = 0; nt < 4; ++nt) {
                unsigned bf[2];
                bf[0] = DVt[(ct*32+nt*8+lr)*68 + ks*8+lc];
                bf[1] = DVt[(ct*32+nt*8+lr)*68 + ks*8+lc+4];
                mma8(macc[nt], a, bf);
            }
        }
    }

    // write partials
    float* mp = g_mpart + (size_t)blockIdx.x * DH*DH;
    int d0 = rt*16 + lr, d1 = d0 + 8;
    #pragma unroll
    for (int nt = 0; nt < 4; ++nt) {
        int c0 = ct*32 + nt*8 + 2*lc;
        *(float2*)&mp[d0*DH + c0] = make_float2(macc[nt][0], macc[nt][1]);
        *(float2*)&mp[d1*DH + c0] = make_float2(macc[nt][2], macc[nt][3]);
    }
    zpart += __shfl_xor_sync(0xffffffffu, zpart, 1);
    zpart += __shfl_xor_sync(0xffffffffu, zpart, 2);
    if (lc == 0) g_zpart[blockIdx.x*DH + dz] = zpart;
}

// ---------------------------------------------------------------------------
// Kernel 3b: reduce partials -> out
// ---------------------------------------------------------------------------
__global__ __launch_bounds__(256)
void state_reduce(const float* __restrict__ M_in, const float* __restrict__ Z_in,
                  const float* __restrict__ beta_lin, float* __restrict__ out) {
    const int bh = blockIdx.x;
    const int tid = threadIdx.x;
    float beta = 1.f / (1.f + __expf(-beta_lin[0]));
    beta = fminf(fmaxf(beta, 0.9f), 0.999f);

    const float* p0 = g_mpart + (size_t)(bh*4 + 0)*DH*DH;
    const float* p1 = g_mpart + (size_t)(bh*4 + 1)*DH*DH;
    const float* p2 = g_mpart + (size_t)(bh*4 + 2)*DH*DH;
    const float* p3 = g_mpart + (size_t)(bh*4 + 3)*DH*DH;
    const float* Mg = M_in + (size_t)bh*DH*DH;
    float* mo = out + A_ELEMS + (size_t)bh*DH*DH;
    for (int e = tid; e < DH*DH; e += 256)
        mo[e] = beta*Mg[e] + p0[e] + p1[e] + p2[e] + p3[e];
    if (tid < DH) {
        float z = g_zpart[(bh*4+0)*DH + tid] + g_zpart[(bh*4+1)*DH + tid]
                + g_zpart[(bh*4+2)*DH + tid] + g_zpart[(bh*4+3)*DH + tid];
        out[A_ELEMS + M_ELEMS + bh*DH + tid] = beta*Z_in[bh*DH + tid] + z;
    }
}

// ---------------------------------------------------------------------------
extern "C" void kernel_launch(void* const* d_in, const int* in_sizes, int n_in,
                              void* d_out, int out_size) {
    const float* x         = (const float*)d_in[0];
    const float* M         = (const float*)d_in[1];
    const float* Z         = (const float*)d_in[2];
    const float* W         = (const float*)d_in[3];
    const float* beta_lin  = (const float*)d_in[4];
    const float* beta_gate = (const float*)d_in[5];
    float* out = (float*)d_out;

    cudaFuncSetAttribute(attn_k, cudaFuncAttributeMaxDynamicSharedMemorySize, ATT_SMEM_BYTES);
    cudaFuncSetAttribute(state_part, cudaFuncAttributeMaxDynamicSharedMemorySize, ST_SMEM_BYTES);

    const int npc = (BB*NQ*DIMK + DIMK*NCOLS)/4;
    preconv<<<(npc + 255)/256, 256>>>(x, W);
    qkv_gemm<<<dim3(NCOLS/128, (BB*NQ)/128), 256>>>();
    attn_k<<<dim3(NQ/128, HEADS, BB), 256, ATT_SMEM_BYTES>>>(M, Z, beta_gate, out);
    state_part<<<BB*HEADS*SPLIT, 256, ST_SMEM_BYTES>>>(M, Z);
    state_reduce<<<BB*HEADS, 256>>>(M, Z, beta_lin, out);
}

// round 7
// speedup vs baseline: 2.4936x; 1.9643x over previous
#include <cuda_runtime.h>
#include <cuda_fp16.h>

#define BB    4
#define NQ    2048
#define DIMK  1024
#define HEADS 16
#define DH    64
#define INNER 1024
#define NCOLS 3072
#define SPLIT 4

#define A_ELEMS (BB*NQ*INNER)
#define M_ELEMS (BB*HEADS*DH*DH)

__device__ float  g_k[BB*HEADS*NQ*DH];
__device__ float  g_v[BB*HEADS*NQ*DH];
__device__ __half g_qh[BB*HEADS*NQ*DH];
__device__ __half g_kh[BB*HEADS*NQ*DH];
__device__ __half g_vh[BB*HEADS*NQ*DH];
__device__ __half g_xh[BB*NQ*DIMK];
__device__ __half g_wh[DIMK*NCOLS];
__device__ float  g_mpart[BB*HEADS*SPLIT*DH*DH];
__device__ float  g_zpart[BB*HEADS*SPLIT*DH];

__device__ __forceinline__ unsigned f2tf(float f) {
    unsigned u; asm("cvt.rna.tf32.f32 %0, %1;" : "=r"(u) : "f"(f)); return u;
}
__device__ __forceinline__ void mma8(float* c, const unsigned* a, const unsigned* b) {
    asm volatile(
        "mma.sync.aligned.m16n8k8.row.col.f32.tf32.tf32.f32 "
        "{%0,%1,%2,%3}, {%4,%5,%6,%7}, {%8,%9}, {%0,%1,%2,%3};\n"
        : "+f"(c[0]), "+f"(c[1]), "+f"(c[2]), "+f"(c[3])
        : "r"(a[0]), "r"(a[1]), "r"(a[2]), "r"(a[3]), "r"(b[0]), "r"(b[1]));
}
__device__ __forceinline__ void mmah(float* c, const unsigned* a, const unsigned* b) {
    asm volatile(
        "mma.sync.aligned.m16n8k16.row.col.f32.f16.f16.f32 "
        "{%0,%1,%2,%3}, {%4,%5,%6,%7}, {%8,%9}, {%0,%1,%2,%3};\n"
        : "+f"(c[0]), "+f"(c[1]), "+f"(c[2]), "+f"(c[3])
        : "r"(a[0]), "r"(a[1]), "r"(a[2]), "r"(a[3]), "r"(b[0]), "r"(b[1]));
}
__device__ __forceinline__ void ldsm_x4(unsigned* r, unsigned addr) {
    asm volatile("ldmatrix.sync.aligned.m8n8.x4.shared.b16 {%0,%1,%2,%3}, [%4];"
        : "=r"(r[0]), "=r"(r[1]), "=r"(r[2]), "=r"(r[3]) : "r"(addr));
}
__device__ __forceinline__ void ldsm_x4_t(unsigned* r, unsigned addr) {
    asm volatile("ldmatrix.sync.aligned.m8n8.x4.trans.shared.b16 {%0,%1,%2,%3}, [%4];"
        : "=r"(r[0]), "=r"(r[1]), "=r"(r[2]), "=r"(r[3]) : "r"(addr));
}
__device__ __forceinline__ unsigned packh2(float a, float b) {
    __half2 h = __floats2half2_rn(a, b);
    return *(unsigned*)&h;
}
__device__ __forceinline__ float sigma_f(float f) {
    return (f > 0.f) ? (f + 1.f) : __expf(f);
}
__device__ __forceinline__ unsigned sptr(const void* p) {
    return (unsigned)__cvta_generic_to_shared(p);
}
#define CP16(dst, src) asm volatile("cp.async.ca.shared.global [%0], [%1], 16;" :: "r"(dst), "l"(src))
#define CP_COMMIT()    asm volatile("cp.async.commit_group;")
#define CP_WAIT0()     asm volatile("cp.async.wait_group 0;")

// ---------------------------------------------------------------------------
// Kernel 0: x, W -> half
// ---------------------------------------------------------------------------
__global__ __launch_bounds__(256)
void preconv(const float* __restrict__ x, const float* __restrict__ W) {
    const int nx = BB*NQ*DIMK/4;
    const int nw = DIMK*NCOLS/4;
    int i = blockIdx.x*256 + threadIdx.x;
    if (i < nx) {
        float4 v = ((const float4*)x)[i];
        ((__half2*)g_xh)[2*i]   = __floats2half2_rn(v.x, v.y);
        ((__half2*)g_xh)[2*i+1] = __floats2half2_rn(v.z, v.w);
    } else if (i < nx + nw) {
        int j = i - nx;
        float4 v = ((const float4*)W)[j];
        ((__half2*)g_wh)[2*j]   = __floats2half2_rn(v.x, v.y);
        ((__half2*)g_wh)[2*j+1] = __floats2half2_rn(v.z, v.w);
    }
}

// ---------------------------------------------------------------------------
// Kernel 1: QKV GEMM fp16 mma (m16n8k16), BK=32, cp.async 2-stage.
// As[2][128][40] half, Bs[2][32][136] half ([k][n], ldsm.trans for B-frags)
// ---------------------------------------------------------------------------
__global__ __launch_bounds__(256, 2)
void qkv_gemm(void) {
    __shared__ __align__(16) __half As[2][128*40];
    __shared__ __align__(16) __half Bs[2][32*136];

    const int tid  = threadIdx.x;
    const int bm   = blockIdx.y * 128, bn = blockIdx.x * 128;
    const int wid  = tid >> 5, lane = tid & 31;
    const int wm   = (wid & 1) * 64, wn = (wid >> 1) * 32;
    const int lr   = lane >> 2, lc = lane & 3;

    // cp.async mapping: A 512 chunks (row = c>>2, ch = c&3), B 512 (row = c>>4, ch = c&15)
    const int ar = tid >> 2, ach = tid & 3;
    const int br = tid >> 4, bch = tid & 15;
    const __half* asrc0 = g_xh + (size_t)(bm + ar) * DIMK + ach*8;
    const __half* asrc1 = asrc0 + (size_t)64 * DIMK;
    const __half* bsrc0 = g_wh + (size_t)br * NCOLS + bn + bch*8;
    const __half* bsrc1 = bsrc0 + (size_t)16 * NCOLS;
    const unsigned a_off = sptr(&As[0][ar*40 + ach*8]);
    const unsigned b_off = sptr(&Bs[0][br*136 + bch*8]);
    #define ASTGH (128*40*2)
    #define BSTGH (32*136*2)

    CP16(a_off, asrc0); CP16(a_off + 64*40*2, asrc1);
    CP16(b_off, bsrc0); CP16(b_off + 16*136*2, bsrc1);
    CP_COMMIT();

    float cacc[4][4][4];
    #pragma unroll
    for (int i = 0; i < 4; i++)
        #pragma unroll
        for (int j = 0; j < 4; j++) { cacc[i][j][0]=0.f; cacc[i][j][1]=0.f; cacc[i][j][2]=0.f; cacc[i][j][3]=0.f; }

    const int l15 = lane & 15;
    const int lhi8 = (lane & 16) >> 1;   // +8 cols for upper half-warp
    int cur = 0;
    for (int kt = 0; kt < DIMK/32; ++kt) {
        CP_WAIT0();
        __syncthreads();
        if (kt + 1 < DIMK/32) {
            int ko = (kt + 1) * 32;
            unsigned ao = a_off + (cur ^ 1)*ASTGH;
            unsigned bo = b_off + (cur ^ 1)*BSTGH;
            CP16(ao, asrc0 + ko);
            CP16(ao + 64*40*2, asrc1 + ko);
            CP16(bo, bsrc0 + (size_t)ko * NCOLS);
            CP16(bo + 16*136*2, bsrc1 + (size_t)ko * NCOLS);
            CP_COMMIT();
        }

        const __half* Ah = As[cur];
        const __half* Bh = Bs[cur];
        #pragma unroll
        for (int ks = 0; ks < 2; ++ks) {
            unsigned af[4][4];
            #pragma unroll
            for (int mt = 0; mt < 4; ++mt)
                ldsm_x4(af[mt], sptr(&Ah[(wm + mt*16 + l15)*40 + ks*16 + lhi8]));
            #pragma unroll
            for (int ntp = 0; ntp < 2; ++ntp) {
                unsigned bf[4];
                ldsm_x4_t(bf, sptr(&Bh[(ks*16 + l15)*136 + wn + ntp*16 + lhi8]));
                #pragma unroll
                for (int mt = 0; mt < 4; ++mt) {
                    mmah(cacc[mt][2*ntp],   af[mt], bf);
                    mmah(cacc[mt][2*ntp+1], af[mt], bf + 2);
                }
            }
        }
        cur ^= 1;
    }

    const int part = (bn + wn) >> 10;
    #pragma unroll
    for (int mt = 0; mt < 4; ++mt) {
        int r0 = bm + wm + mt*16 + lr;
        #pragma unroll
        for (int nt = 0; nt < 4; ++nt) {
            int cg = bn + wn + nt*8 + 2*lc;
            int hh = (cg >> 6) & (HEADS - 1);
            int dd = cg & 63;
            int bi = r0 >> 11, nn = r0 & 2047;
            size_t off = (((size_t)(bi*HEADS + hh) * NQ + nn) * DH) + dd;
            int r1 = r0 + 8;
            int bi1 = r1 >> 11, nn1 = r1 & 2047;
            size_t off2 = (((size_t)(bi1*HEADS + hh) * NQ + nn1) * DH) + dd;
            unsigned h0 = packh2(cacc[mt][nt][0], cacc[mt][nt][1]);
            unsigned h1 = packh2(cacc[mt][nt][2], cacc[mt][nt][3]);
            if (part == 0) {
                *(unsigned*)&g_qh[off]  = h0;
                *(unsigned*)&g_qh[off2] = h1;
            } else if (part == 1) {
                *(unsigned*)&g_kh[off]  = h0;
                *(unsigned*)&g_kh[off2] = h1;
                *(float2*)&g_k[off]  = make_float2(cacc[mt][nt][0], cacc[mt][nt][1]);
                *(float2*)&g_k[off2] = make_float2(cacc[mt][nt][2], cacc[mt][nt][3]);
            } else {
                *(unsigned*)&g_vh[off]  = h0;
                *(unsigned*)&g_vh[off2] = h1;
                *(float2*)&g_v[off]  = make_float2(cacc[mt][nt][0], cacc[mt][nt][1]);
                *(float2*)&g_v[off2] = make_float2(cacc[mt][nt][2], cacc[mt][nt][3]);
            }
        }
    }
}

// ---------------------------------------------------------------------------
// Kernel 2: fp16 flash attention + memory branch.
// smem: Kh[2][64*72] | Vh[2][64*72] halfs | Zs[64] floats
// K B-frags: ldsm non-trans; V/M B-frags: ldsm trans; P->A: direct cvt packs.
// ---------------------------------------------------------------------------
#define KTILEH (64*72)
#define ATT_SMEM_BYTES (4*KTILEH*2 + 64*4)
#define SCL2 0.1803368801111204f   // 0.125 * log2(e)

__global__ __launch_bounds__(256, 2)
void attn_k(const float* __restrict__ M_in, const float* __restrict__ Z_in,
            const float* __restrict__ beta_gate, float* __restrict__ outA) {
    extern __shared__ __align__(16) __half smh[];
    __half* KH = smh;                    // [2][64*72]
    __half* VH = smh + 2*KTILEH;         // [2][64*72]
    float*  Zs = (float*)(smh + 4*KTILEH);

    const int tid = threadIdx.x, wid = tid >> 5, lane = tid & 31;
    const int lr = lane >> 2, lc = lane & 3;
    const int l15 = lane & 15;
    const int l7  = lane & 7;
    const int lhi8 = (lane & 16) >> 1;
    const int b = blockIdx.z, h = blockIdx.y, bh = b*HEADS + h;
    const int qb = blockIdx.x * 128;
    const int rowA = wid*16 + lr;

    const __half* qg = g_qh + ((size_t)bh*NQ + qb)*DH;
    const __half* kg = g_kh + (size_t)bh*NQ*DH;
    const __half* vg = g_vh + (size_t)bh*NQ*DH;

    // cp.async mapping: 512 chunks per tile, 2/thread (rows tid>>3 and +32)
    const int cr = tid >> 3, cch = tid & 7;
    const unsigned k_off = sptr(&KH[cr*72 + cch*8]);
    const unsigned v_off = sptr(&VH[cr*72 + cch*8]);
    const __half* ksrc = kg + (size_t)cr*DH + cch*8;
    const __half* vsrc = vg + (size_t)cr*DH + cch*8;
    #define ROW32H (32*72*2)

    // Q fragments: 16 LDG.32 one-time
    unsigned qa[4][4];
    #pragma unroll
    for (int ks = 0; ks < 4; ++ks) {
        qa[ks][0] = *(const unsigned*)&qg[(size_t)rowA*DH + ks*16 + 2*lc];
        qa[ks][1] = *(const unsigned*)&qg[(size_t)(rowA+8)*DH + ks*16 + 2*lc];
        qa[ks][2] = *(const unsigned*)&qg[(size_t)rowA*DH + ks*16 + 2*lc + 8];
        qa[ks][3] = *(const unsigned*)&qg[(size_t)(rowA+8)*DH + ks*16 + 2*lc + 8];
    }

    CP16(k_off, ksrc); CP16(k_off + ROW32H, ksrc + 32*DH);
    CP16(v_off, vsrc); CP16(v_off + ROW32H, vsrc + 32*DH);
    CP_COMMIT();

    float oacc[8][4];
    #pragma unroll
    for (int i = 0; i < 8; i++) { oacc[i][0]=0.f; oacc[i][1]=0.f; oacc[i][2]=0.f; oacc[i][3]=0.f; }
    float m1 = -1e30f, m2 = -1e30f, l1 = 0.f, l2 = 0.f;

    int cur = 0;
    for (int jt = 0; jt < NQ; jt += 64) {
        CP_WAIT0();
        __syncthreads();
        if (jt + 64 < NQ) {
            int nx = cur ^ 1;
            const __half* kn = ksrc + (size_t)(jt + 64)*DH;
            const __half* vn = vsrc + (size_t)(jt + 64)*DH;
            CP16(k_off + nx*KTILEH*2, kn); CP16(k_off + nx*KTILEH*2 + ROW32H, kn + 32*DH);
            CP16(v_off + nx*KTILEH*2, vn); CP16(v_off + nx*KTILEH*2 + ROW32H, vn + 32*DH);
            CP_COMMIT();
        }
        const __half* Kc = KH + cur*KTILEH;
        const __half* Vc = VH + cur*KTILEH;

        // S = Q K^T
        float sacc[8][4];
        #pragma unroll
        for (int i = 0; i < 8; i++) { sacc[i][0]=0.f; sacc[i][1]=0.f; sacc[i][2]=0.f; sacc[i][3]=0.f; }
        #pragma unroll
        for (int ks = 0; ks < 4; ++ks) {
            #pragma unroll
            for (int ntp = 0; ntp < 4; ++ntp) {
                unsigned kb[4];
                ldsm_x4(kb, sptr(&Kc[(ntp*16 + l7 + lhi8)*72 + ks*16 + (lane & 8)]));
                mmah(sacc[2*ntp],   qa[ks], kb);
                mmah(sacc[2*ntp+1], qa[ks], kb + 2);
            }
        }

        // online softmax (base-2)
        float tmax1 = -1e30f, tmax2 = -1e30f;
        #pragma unroll
        for (int nt = 0; nt < 8; ++nt) {
            tmax1 = fmaxf(tmax1, fmaxf(sacc[nt][0], sacc[nt][1]));
            tmax2 = fmaxf(tmax2, fmaxf(sacc[nt][2], sacc[nt][3]));
        }
        tmax1 = fmaxf(tmax1, __shfl_xor_sync(0xffffffffu, tmax1, 1));
        tmax1 = fmaxf(tmax1, __shfl_xor_sync(0xffffffffu, tmax1, 2));
        tmax2 = fmaxf(tmax2, __shfl_xor_sync(0xffffffffu, tmax2, 1));
        tmax2 = fmaxf(tmax2, __shfl_xor_sync(0xffffffffu, tmax2, 2));

        float mn1 = fmaxf(m1, tmax1*SCL2), mn2 = fmaxf(m2, tmax2*SCL2);
        float corr1 = exp2f(m1 - mn1), corr2 = exp2f(m2 - mn2);
        float rs1 = 0.f, rs2 = 0.f;
        #pragma unroll
        for (int nt = 0; nt < 8; ++nt) {
            sacc[nt][0] = exp2f(sacc[nt][0]*SCL2 - mn1);
            sacc[nt][1] = exp2f(sacc[nt][1]*SCL2 - mn1);
            sacc[nt][2] = exp2f(sacc[nt][2]*SCL2 - mn2);
            sacc[nt][3] = exp2f(sacc[nt][3]*SCL2 - mn2);
            rs1 += sacc[nt][0] + sacc[nt][1];
            rs2 += sacc[nt][2] + sacc[nt][3];
        }
        rs1 += __shfl_xor_sync(0xffffffffu, rs1, 1);
        rs1 += __shfl_xor_sync(0xffffffffu, rs1, 2);
        rs2 += __shfl_xor_sync(0xffffffffu, rs2, 1);
        rs2 += __shfl_xor_sync(0xffffffffu, rs2, 2);
        l1 = l1*corr1 + rs1;
        l2 = l2*corr2 + rs2;
        #pragma unroll
        for (int nt = 0; nt < 8; ++nt) {
            oacc[nt][0] *= corr1; oacc[nt][1] *= corr1;
            oacc[nt][2] *= corr2; oacc[nt][3] *= corr2;
        }
        m1 = mn1; m2 = mn2;

        // O += P V : A-frag = packed C-frag (no shuffles)
        #pragma unroll
        for (int ks = 0; ks < 4; ++ks) {
            unsigned a[4];
            a[0] = packh2(sacc[2*ks][0],   sacc[2*ks][1]);
            a[1] = packh2(sacc[2*ks][2],   sacc[2*ks][3]);
            a[2] = packh2(sacc[2*ks+1][0], sacc[2*ks+1][1]);
            a[3] = packh2(sacc[2*ks+1][2], sacc[2*ks+1][3]);
            #pragma unroll
            for (int ntp = 0; ntp < 4; ++ntp) {
                unsigned vb[4];
                ldsm_x4_t(vb, sptr(&Vc[(ks*16 + l15)*72 + ntp*16 + lhi8]));
                mmah(oacc[2*ntp],   a, vb);
                mmah(oacc[2*ntp+1], a, vb + 2);
            }
        }
        cur ^= 1;
    }

    // epilogue: A_mem = sigma(Q) @ M via fp16 mma; Mh staged in KH[0]
    __syncthreads();
    const float* Mg = M_in + (size_t)bh*DH*DH;
    __half* Mh = KH;                      // [d][v], stride 72
    for (int i = tid; i < DH*DH; i += 256) {
        int d = i >> 6, v = i & 63;
        Mh[d*72 + v] = __float2half_rn(Mg[i]);
    }
    if (tid < DH) Zs[tid] = Z_in[bh*DH + tid];
    __syncthreads();

    float macc[8][4];
    #pragma unroll
    for (int i = 0; i < 8; i++) { macc[i][0]=0.f; macc[i][1]=0.f; macc[i][2]=0.f; macc[i][3]=0.f; }
    float den1 = 0.f, den2 = 0.f;

    #pragma unroll
    for (int ks = 0; ks < 4; ++ks) {
        unsigned a[4];
        int c0 = ks*16 + 2*lc;
        float2 f0 = __half22float2(*(__half2*)&qa[ks][0]);
        float2 f1 = __half22float2(*(__half2*)&qa[ks][1]);
        float2 f2 = __half22float2(*(__half2*)&qa[ks][2]);
        float2 f3 = __half22float2(*(__half2*)&qa[ks][3]);
        float s00 = sigma_f(f0.x), s01 = sigma_f(f0.y);
        float s10 = sigma_f(f1.x), s11 = sigma_f(f1.y);
        float s20 = sigma_f(f2.x), s21 = sigma_f(f2.y);
        float s30 = sigma_f(f3.x), s31 = sigma_f(f3.y);
        a[0] = packh2(s00, s01); a[1] = packh2(s10, s11);
        a[2] = packh2(s20, s21); a[3] = packh2(s30, s31);
        den1 += s00*Zs[c0] + s01*Zs[c0+1] + s20*Zs[c0+8] + s21*Zs[c0+9];
        den2 += s10*Zs[c0] + s11*Zs[c0+1] + s30*Zs[c0+8] + s31*Zs[c0+9];
        #pragma unroll
        for (int ntp = 0; ntp < 4; ++ntp) {
            unsigned mb[4];
            ldsm_x4_t(mb, sptr(&Mh[(ks*16 + l15)*72 + ntp*16 + lhi8]));
            mmah(macc[2*ntp],   a, mb);
            mmah(macc[2*ntp+1], a, mb + 2);
        }
    }
    den1 += __shfl_xor_sync(0xffffffffu, den1, 1);
    den1 += __shfl_xor_sync(0xffffffffu, den1, 2);
    den2 += __shfl_xor_sync(0xffffffffu, den2, 1);
    den2 += __shfl_xor_sync(0xffffffffu, den2, 2);

    float g = 1.f / (1.f + __expf(-beta_gate[h]));
    float iv1 = 1.f/l1, iv2 = 1.f/l2, id1 = 1.f/den1, id2 = 1.f/den2;

    int n1 = qb + rowA;
    float* o1 = outA + ((size_t)(b*NQ + n1))*INNER + h*DH;
    float* o2 = o1 + (size_t)8*INNER;
    #pragma unroll
    for (int nt = 0; nt < 8; ++nt) {
        int d = nt*8 + 2*lc;
        *(float2*)&o1[d] = make_float2(
            g*macc[nt][0]*id1 + (1.f-g)*oacc[nt][0]*iv1,
            g*macc[nt][1]*id1 + (1.f-g)*oacc[nt][1]*iv1);
        *(float2*)&o2[d] = make_float2(
            g*macc[nt][2]*id2 + (1.f-g)*oacc[nt][2]*iv2,
            g*macc[nt][3]*id2 + (1.f-g)*oacc[nt][3]*iv2);
    }
}

// ---------------------------------------------------------------------------
// Kernel 3a: state partials via tf32 mma (unchanged from R6)
// ---------------------------------------------------------------------------
#define ST_SMEM_WORDS (4*64*68 + 128)
#define ST_SMEM_BYTES (ST_SMEM_WORDS*4)

__global__ __launch_bounds__(256)
void state_part(const float* __restrict__ M_in, const float* __restrict__ Z_in) {
    extern __shared__ float ssm[];
    unsigned* Sks = (unsigned*)ssm;
    float*    Vs  = ssm + 64*68;
    unsigned* DVt = (unsigned*)(ssm + 2*64*68);
    unsigned* Mt  = (unsigned*)(ssm + 3*64*68);
    float*    Zs  = ssm + 4*64*68;
    float*    invden = Zs + 64;

    const int tid = threadIdx.x, wid = tid >> 5, lane = tid & 31;
    const int lr = lane >> 2, lc = lane & 3;
    const int bh = blockIdx.x >> 2;
    const int chunk = blockIdx.x & 3;
    const int nrows = NQ / SPLIT;
    const int rt = wid & 3, ct = wid >> 2;

    const float* Mg = M_in + (size_t)bh*DH*DH;
    for (int i = tid; i < DH*DH; i += 256) {
        int d = i >> 6, v = i & 63;
        Mt[v*68 + d] = f2tf(Mg[i]);
    }
    if (tid < DH) Zs[tid] = Z_in[bh*DH + tid];

    const float* kg = g_k + ((size_t)bh*NQ + (size_t)chunk*nrows)*DH;
    const float* vg = g_v + ((size_t)bh*NQ + (size_t)chunk*nrows)*DH;

    float macc[4][4];
    #pragma unroll
    for (int i = 0; i < 4; i++) { macc[i][0]=0.f; macc[i][1]=0.f; macc[i][2]=0.f; macc[i][3]=0.f; }
    float zpart = 0.f;
    const int dz = wid*8 + lr;

    for (int n0 = 0; n0 < nrows; n0 += 64) {
        __syncthreads();
        #pragma unroll
        for (int t = 0; t < 4; ++t) {
            int idx = tid + 256*t;
            int r = idx >> 4, c4 = (idx & 15) << 2;
            float4 kv = *(const float4*)&kg[(size_t)(n0+r)*DH + c4];
            kv.x = sigma_f(kv.x); kv.y = sigma_f(kv.y);
            kv.z = sigma_f(kv.z); kv.w = sigma_f(kv.w);
            *(uint4*)&Sks[r*68 + c4] = make_uint4(f2tf(kv.x), f2tf(kv.y), f2tf(kv.z), f2tf(kv.w));
            *(float4*)&Vs[r*68 + c4] = *(const float4*)&vg[(size_t)(n0+r)*DH + c4];
        }
        __syncthreads();

        {
            int rn = wid*8 + lr;
            float acc = 0.f;
            #pragma unroll
            for (int j = 0; j < 16; ++j) {
                int d = lc*16 + j;
                acc += __uint_as_float(Sks[rn*68 + d]) * Zs[d];
            }
            acc += __shfl_xor_sync(0xffffffffu, acc, 1);
            acc += __shfl_xor_sync(0xffffffffu, acc, 2);
            if (lc == 0) invden[rn] = 1.f / acc;
            #pragma unroll
            for (int j = 0; j < 16; ++j)
                zpart += __uint_as_float(Sks[(lc*16 + j)*68 + dz]);
        }
        __syncthreads();

        float pacc[4][4];
        #pragma unroll
        for (int i = 0; i < 4; i++) { pacc[i][0]=0.f; pacc[i][1]=0.f; pacc[i][2]=0.f; pacc[i][3]=0.f; }
        #pragma unroll
        for (int ks = 0; ks < 8; ++ks) {
            unsigned a[4];
            a[0] = Sks[(rt*16+lr)*68 + ks*8+lc];
            a[1] = Sks[(rt*16+lr+8)*68 + ks*8+lc];
            a[2] = Sks[(rt*16+lr)*68 + ks*8+lc+4];
            a[3] = Sks[(rt*16+lr+8)*68 + ks*8+lc+4];
            #pragma unroll
            for (int nt = 0; nt < 4; ++nt) {
                unsigned bf[2];
                bf[0] = Mt[(ct*32+nt*8+lr)*68 + ks*8+lc];
                bf[1] = Mt[(ct*32+nt*8+lr)*68 + ks*8+lc+4];
                mma8(pacc[nt], a, bf);
            }
        }

        {
            int r0 = rt*16 + lr, r1 = r0 + 8;
            float iv0 = invden[r0], iv1 = invden[r1];
            #pragma unroll
            for (int nt = 0; nt < 4; ++nt) {
                int c0 = ct*32 + nt*8 + 2*lc, c1 = c0 + 1;
                DVt[c0*68 + r0] = f2tf(Vs[r0*68 + c0] - pacc[nt][0]*iv0);
                DVt[c1*68 + r0] = f2tf(Vs[r0*68 + c1] - pacc[nt][1]*iv0);
                DVt[c0*68 + r1] = f2tf(Vs[r1*68 + c0] - pacc[nt][2]*iv1);
                DVt[c1*68 + r1] = f2tf(Vs[r1*68 + c1] - pacc[nt][3]*iv1);
            }
        }
        __syncthreads();

        #pragma unroll
        for (int ks = 0; ks < 8; ++ks) {
            unsigned a[4];
            a[0] = Sks[(ks*8+lc)*68 + rt*16+lr];
            a[1] = Sks[(ks*8+lc)*68 + rt*16+lr+8];
            a[2] = Sks[(ks*8+lc+4)*68 + rt*16+lr];
            a[3] = Sks[(ks*8+lc+4)*68 + rt*16+lr+8];
            #pragma unroll
            for (int nt = 0; nt < 4; ++nt) {
                unsigned bf[2];
                bf[0] = DVt[(ct*32+nt*8+lr)*68 + ks*8+lc];
                bf[1] = DVt[(ct*32+nt*8+lr)*68 + ks*8+lc+4];
                mma8(macc[nt], a, bf);
            }
        }
    }

    float* mp = g_mpart + (size_t)blockIdx.x * DH*DH;
    int d0 = rt*16 + lr, d1 = d0 + 8;
    #pragma unroll
    for (int nt = 0; nt < 4; ++nt) {
        int c0 = ct*32 + nt*8 + 2*lc;
        *(float2*)&mp[d0*DH + c0] = make_float2(macc[nt][0], macc[nt][1]);
        *(float2*)&mp[d1*DH + c0] = make_float2(macc[nt][2], macc[nt][3]);
    }
    zpart += __shfl_xor_sync(0xffffffffu, zpart, 1);
    zpart += __shfl_xor_sync(0xffffffffu, zpart, 2);
    if (lc == 0) g_zpart[blockIdx.x*DH + dz] = zpart;
}

// ---------------------------------------------------------------------------
// Kernel 3b: reduce partials -> out
// ---------------------------------------------------------------------------
__global__ __launch_bounds__(256)
void state_reduce(const float* __restrict__ M_in, const float* __restrict__ Z_in,
                  const float* __restrict__ beta_lin, float* __restrict__ out) {
    const int bh = blockIdx.x;
    const int tid = threadIdx.x;
    float beta = 1.f / (1.f + __expf(-beta_lin[0]));
    beta = fminf(fmaxf(beta, 0.9f), 0.999f);

    const float* p0 = g_mpart + (size_t)(bh*4 + 0)*DH*DH;
    const float* p1 = g_mpart + (size_t)(bh*4 + 1)*DH*DH;
    const float* p2 = g_mpart + (size_t)(bh*4 + 2)*DH*DH;
    const float* p3 = g_mpart + (size_t)(bh*4 + 3)*DH*DH;
    const float* Mg = M_in + (size_t)bh*DH*DH;
    float* mo = out + A_ELEMS + (size_t)bh*DH*DH;
    for (int e = tid; e < DH*DH; e += 256)
        mo[e] = beta*Mg[e] + p0[e] + p1[e] + p2[e] + p3[e];
    if (tid < DH) {
        float z = g_zpart[(bh*4+0)*DH + tid] + g_zpart[(bh*4+1)*DH + tid]
                + g_zpart[(bh*4+2)*DH + tid] + g_zpart[(bh*4+3)*DH + tid];
        out[A_ELEMS + M_ELEMS + bh*DH + tid] = beta*Z_in[bh*DH + tid] + z;
    }
}

// ---------------------------------------------------------------------------
extern "C" void kernel_launch(void* const* d_in, const int* in_sizes, int n_in,
                              void* d_out, int out_size) {
    const float* x         = (const float*)d_in[0];
    const float* M         = (const float*)d_in[1];
    const float* Z         = (const float*)d_in[2];
    const float* W         = (const float*)d_in[3];
    const float* beta_lin  = (const float*)d_in[4];
    const float* beta_gate = (const float*)d_in[5];
    float* out = (float*)d_out;

    cudaFuncSetAttribute(attn_k, cudaFuncAttributeMaxDynamicSharedMemorySize, ATT_SMEM_BYTES);
    cudaFuncSetAttribute(state_part, cudaFuncAttributeMaxDynamicSharedMemorySize, ST_SMEM_BYTES);

    const int npc = (BB*NQ*DIMK + DIMK*NCOLS)/4;
    preconv<<<(npc + 255)/256, 256>>>(x, W);
    qkv_gemm<<<dim3(NCOLS/128, (BB*NQ)/128), 256>>>();
    attn_k<<<dim3(NQ/128, HEADS, BB), 256, ATT_SMEM_BYTES>>>(M, Z, beta_gate, out);
    state_part<<<BB*HEADS*SPLIT, 256, ST_SMEM_BYTES>>>(M, Z);
    state_reduce<<<BB*HEADS, 256>>>(M, Z, beta_lin, out);
}

// round 8
// speedup vs baseline: 2.6213x; 1.0512x over previous
#include <cuda_runtime.h>
#include <cuda_fp16.h>

#define BB    4
#define NQ    2048
#define DIMK  1024
#define HEADS 16
#define DH    64
#define INNER 1024
#define NCOLS 3072
#define SPLIT 8

#define A_ELEMS (BB*NQ*INNER)
#define M_ELEMS (BB*HEADS*DH*DH)

__device__ __half g_qh[BB*HEADS*NQ*DH];
__device__ __half g_kh[BB*HEADS*NQ*DH];
__device__ __half g_vh[BB*HEADS*NQ*DH];
__device__ __half g_xh[BB*NQ*DIMK];
__device__ __half g_wh[DIMK*NCOLS];
__device__ float  g_mpart[BB*HEADS*SPLIT*DH*DH];
__device__ float  g_zpart[BB*HEADS*SPLIT*DH];

__device__ __forceinline__ unsigned f2tf(float f) {
    unsigned u; asm("cvt.rna.tf32.f32 %0, %1;" : "=r"(u) : "f"(f)); return u;
}
__device__ __forceinline__ void mma8(float* c, const unsigned* a, const unsigned* b) {
    asm volatile(
        "mma.sync.aligned.m16n8k8.row.col.f32.tf32.tf32.f32 "
        "{%0,%1,%2,%3}, {%4,%5,%6,%7}, {%8,%9}, {%0,%1,%2,%3};\n"
        : "+f"(c[0]), "+f"(c[1]), "+f"(c[2]), "+f"(c[3])
        : "r"(a[0]), "r"(a[1]), "r"(a[2]), "r"(a[3]), "r"(b[0]), "r"(b[1]));
}
__device__ __forceinline__ void mmah(float* c, const unsigned* a, const unsigned* b) {
    asm volatile(
        "mma.sync.aligned.m16n8k16.row.col.f32.f16.f16.f32 "
        "{%0,%1,%2,%3}, {%4,%5,%6,%7}, {%8,%9}, {%0,%1,%2,%3};\n"
        : "+f"(c[0]), "+f"(c[1]), "+f"(c[2]), "+f"(c[3])
        : "r"(a[0]), "r"(a[1]), "r"(a[2]), "r"(a[3]), "r"(b[0]), "r"(b[1]));
}
__device__ __forceinline__ void ldsm_x4(unsigned* r, unsigned addr) {
    asm volatile("ldmatrix.sync.aligned.m8n8.x4.shared.b16 {%0,%1,%2,%3}, [%4];"
        : "=r"(r[0]), "=r"(r[1]), "=r"(r[2]), "=r"(r[3]) : "r"(addr));
}
__device__ __forceinline__ void ldsm_x4_t(unsigned* r, unsigned addr) {
    asm volatile("ldmatrix.sync.aligned.m8n8.x4.trans.shared.b16 {%0,%1,%2,%3}, [%4];"
        : "=r"(r[0]), "=r"(r[1]), "=r"(r[2]), "=r"(r[3]) : "r"(addr));
}
__device__ __forceinline__ unsigned packh2(float a, float b) {
    __half2 h = __floats2half2_rn(a, b);
    return *(unsigned*)&h;
}
__device__ __forceinline__ float sigma_f(float f) {
    return (f > 0.f) ? (f + 1.f) : __expf(f);
}
__device__ __forceinline__ unsigned sptr(const void* p) {
    return (unsigned)__cvta_generic_to_shared(p);
}
#define CP16(dst, src) asm volatile("cp.async.ca.shared.global [%0], [%1], 16;" :: "r"(dst), "l"(src))
#define CP_COMMIT()    asm volatile("cp.async.commit_group;")
#define CP_WAIT0()     asm volatile("cp.async.wait_group 0;")
#define CP_WAIT1()     asm volatile("cp.async.wait_group 1;")

// ---------------------------------------------------------------------------
// Kernel 0: x, W -> half
// ---------------------------------------------------------------------------
__global__ __launch_bounds__(256)
void preconv(const float* __restrict__ x, const float* __restrict__ W) {
    const int nx = BB*NQ*DIMK/4;
    const int nw = DIMK*NCOLS/4;
    int i = blockIdx.x*256 + threadIdx.x;
    if (i < nx) {
        float4 v = ((const float4*)x)[i];
        ((__half2*)g_xh)[2*i]   = __floats2half2_rn(v.x, v.y);
        ((__half2*)g_xh)[2*i+1] = __floats2half2_rn(v.z, v.w);
    } else if (i < nx + nw) {
        int j = i - nx;
        float4 v = ((const float4*)W)[j];
        ((__half2*)g_wh)[2*j]   = __floats2half2_rn(v.x, v.y);
        ((__half2*)g_wh)[2*j+1] = __floats2half2_rn(v.z, v.w);
    }
}

// ---------------------------------------------------------------------------
// Kernel 1: QKV GEMM fp16 mma, BK=32, 3-stage cp.async pipeline (dyn smem)
// As[3][128*40], Bs[3][32*136] halfs
// ---------------------------------------------------------------------------
#define QA_STG (128*40)
#define QB_STG (32*136)
#define QKV_SMEM_BYTES ((3*QA_STG + 3*QB_STG)*2)

__global__ __launch_bounds__(256, 2)
void qkv_gemm(void) {
    extern __shared__ __align__(16) __half qsm[];
    __half* As = qsm;
    __half* Bs = qsm + 3*QA_STG;

    const int tid  = threadIdx.x;
    const int bm   = blockIdx.y * 128, bn = blockIdx.x * 128;
    const int wid  = tid >> 5, lane = tid & 31;
    const int wm   = (wid & 1) * 64, wn = (wid >> 1) * 32;
    const int lr   = lane >> 2, lc = lane & 3;

    const int ar = tid >> 2, ach = tid & 3;
    const int br = tid >> 4, bch = tid & 15;
    const __half* asrc0 = g_xh + (size_t)(bm + ar) * DIMK + ach*8;
    const __half* asrc1 = asrc0 + (size_t)64 * DIMK;
    const __half* bsrc0 = g_wh + (size_t)br * NCOLS + bn + bch*8;
    const __half* bsrc1 = bsrc0 + (size_t)16 * NCOLS;
    const unsigned a_off = sptr(&As[ar*40 + ach*8]);
    const unsigned b_off = sptr(&Bs[br*136 + bch*8]);

    // prologue: stages 0,1
    #pragma unroll
    for (int s = 0; s < 2; ++s) {
        int ko = s * 32;
        CP16(a_off + s*QA_STG*2, asrc0 + ko);
        CP16(a_off + s*QA_STG*2 + 64*40*2, asrc1 + ko);
        CP16(b_off + s*QB_STG*2, bsrc0 + (size_t)ko * NCOLS);
        CP16(b_off + s*QB_STG*2 + 16*136*2, bsrc1 + (size_t)ko * NCOLS);
        CP_COMMIT();
    }

    float cacc[4][4][4];
    #pragma unroll
    for (int i = 0; i < 4; i++)
        #pragma unroll
        for (int j = 0; j < 4; j++) { cacc[i][j][0]=0.f; cacc[i][j][1]=0.f; cacc[i][j][2]=0.f; cacc[i][j][3]=0.f; }

    const int l15 = lane & 15;
    const int lhi8 = (lane & 16) >> 1;
    int cur = 0;
    for (int kt = 0; kt < DIMK/32; ++kt) {
        CP_WAIT1();
        __syncthreads();
        if (kt + 2 < DIMK/32) {
            int ko = (kt + 2) * 32;
            int nxs = (cur + 2) % 3;
            CP16(a_off + nxs*QA_STG*2, asrc0 + ko);
            CP16(a_off + nxs*QA_STG*2 + 64*40*2, asrc1 + ko);
            CP16(b_off + nxs*QB_STG*2, bsrc0 + (size_t)ko * NCOLS);
            CP16(b_off + nxs*QB_STG*2 + 16*136*2, bsrc1 + (size_t)ko * NCOLS);
            CP_COMMIT();
        }

        const __half* Ah = As + cur*QA_STG;
        const __half* Bh = Bs + cur*QB_STG;
        #pragma unroll
        for (int ks = 0; ks < 2; ++ks) {
            unsigned af[4][4];
            #pragma unroll
            for (int mt = 0; mt < 4; ++mt)
                ldsm_x4(af[mt], sptr(&Ah[(wm + mt*16 + l15)*40 + ks*16 + lhi8]));
            #pragma unroll
            for (int ntp = 0; ntp < 2; ++ntp) {
                unsigned bf[4];
                ldsm_x4_t(bf, sptr(&Bh[(ks*16 + l15)*136 + wn + ntp*16 + lhi8]));
                #pragma unroll
                for (int mt = 0; mt < 4; ++mt) {
                    mmah(cacc[mt][2*ntp],   af[mt], bf);
                    mmah(cacc[mt][2*ntp+1], af[mt], bf + 2);
                }
            }
        }
        cur = (cur + 1) % 3;
    }

    const int part = (bn + wn) >> 10;
    __half* dst = (part == 0) ? g_qh : (part == 1) ? g_kh : g_vh;
    #pragma unroll
    for (int mt = 0; mt < 4; ++mt) {
        int r0 = bm + wm + mt*16 + lr;
        #pragma unroll
        for (int nt = 0; nt < 4; ++nt) {
            int cg = bn + wn + nt*8 + 2*lc;
            int hh = (cg >> 6) & (HEADS - 1);
            int dd = cg & 63;
            int bi = r0 >> 11, nn = r0 & 2047;
            size_t off = (((size_t)(bi*HEADS + hh) * NQ + nn) * DH) + dd;
            int r1 = r0 + 8;
            int bi1 = r1 >> 11, nn1 = r1 & 2047;
            size_t off2 = (((size_t)(bi1*HEADS + hh) * NQ + nn1) * DH) + dd;
            *(unsigned*)&dst[off]  = packh2(cacc[mt][nt][0], cacc[mt][nt][1]);
            *(unsigned*)&dst[off2] = packh2(cacc[mt][nt][2], cacc[mt][nt][3]);
        }
    }
}

// ---------------------------------------------------------------------------
// Kernel 2: fp16 flash attention + memory branch (unchanged from R7)
// ---------------------------------------------------------------------------
#define KTILEH (64*72)
#define ATT_SMEM_BYTES (4*KTILEH*2 + 64*4)
#define SCL2 0.1803368801111204f

__global__ __launch_bounds__(256, 2)
void attn_k(const float* __restrict__ M_in, const float* __restrict__ Z_in,
            const float* __restrict__ beta_gate, float* __restrict__ outA) {
    extern __shared__ __align__(16) __half smh[];
    __half* KH = smh;
    __half* VH = smh + 2*KTILEH;
    float*  Zs = (float*)(smh + 4*KTILEH);

    const int tid = threadIdx.x, wid = tid >> 5, lane = tid & 31;
    const int lr = lane >> 2, lc = lane & 3;
    const int l15 = lane & 15;
    const int l7  = lane & 7;
    const int lhi8 = (lane & 16) >> 1;
    const int b = blockIdx.z, h = blockIdx.y, bh = b*HEADS + h;
    const int qb = blockIdx.x * 128;
    const int rowA = wid*16 + lr;

    const __half* qg = g_qh + ((size_t)bh*NQ + qb)*DH;
    const __half* kg = g_kh + (size_t)bh*NQ*DH;
    const __half* vg = g_vh + (size_t)bh*NQ*DH;

    const int cr = tid >> 3, cch = tid & 7;
    const unsigned k_off = sptr(&KH[cr*72 + cch*8]);
    const unsigned v_off = sptr(&VH[cr*72 + cch*8]);
    const __half* ksrc = kg + (size_t)cr*DH + cch*8;
    const __half* vsrc = vg + (size_t)cr*DH + cch*8;
    #define ROW32H (32*72*2)

    unsigned qa[4][4];
    #pragma unroll
    for (int ks = 0; ks < 4; ++ks) {
        qa[ks][0] = *(const unsigned*)&qg[(size_t)rowA*DH + ks*16 + 2*lc];
        qa[ks][1] = *(const unsigned*)&qg[(size_t)(rowA+8)*DH + ks*16 + 2*lc];
        qa[ks][2] = *(const unsigned*)&qg[(size_t)rowA*DH + ks*16 + 2*lc + 8];
        qa[ks][3] = *(const unsigned*)&qg[(size_t)(rowA+8)*DH + ks*16 + 2*lc + 8];
    }

    CP16(k_off, ksrc); CP16(k_off + ROW32H, ksrc + 32*DH);
    CP16(v_off, vsrc); CP16(v_off + ROW32H, vsrc + 32*DH);
    CP_COMMIT();

    float oacc[8][4];
    #pragma unroll
    for (int i = 0; i < 8; i++) { oacc[i][0]=0.f; oacc[i][1]=0.f; oacc[i][2]=0.f; oacc[i][3]=0.f; }
    float m1 = -1e30f, m2 = -1e30f, l1 = 0.f, l2 = 0.f;

    int cur = 0;
    for (int jt = 0; jt < NQ; jt += 64) {
        CP_WAIT0();
        __syncthreads();
        if (jt + 64 < NQ) {
            int nx = cur ^ 1;
            const __half* kn = ksrc + (size_t)(jt + 64)*DH;
            const __half* vn = vsrc + (size_t)(jt + 64)*DH;
            CP16(k_off + nx*KTILEH*2, kn); CP16(k_off + nx*KTILEH*2 + ROW32H, kn + 32*DH);
            CP16(v_off + nx*KTILEH*2, vn); CP16(v_off + nx*KTILEH*2 + ROW32H, vn + 32*DH);
            CP_COMMIT();
        }
        const __half* Kc = KH + cur*KTILEH;
        const __half* Vc = VH + cur*KTILEH;

        float sacc[8][4];
        #pragma unroll
        for (int i = 0; i < 8; i++) { sacc[i][0]=0.f; sacc[i][1]=0.f; sacc[i][2]=0.f; sacc[i][3]=0.f; }
        #pragma unroll
        for (int ks = 0; ks < 4; ++ks) {
            #pragma unroll
            for (int ntp = 0; ntp < 4; ++ntp) {
                unsigned kb[4];
                ldsm_x4(kb, sptr(&Kc[(ntp*16 + l7 + lhi8)*72 + ks*16 + (lane & 8)]));
                mmah(sacc[2*ntp],   qa[ks], kb);
                mmah(sacc[2*ntp+1], qa[ks], kb + 2);
            }
        }

        float tmax1 = -1e30f, tmax2 = -1e30f;
        #pragma unroll
        for (int nt = 0; nt < 8; ++nt) {
            tmax1 = fmaxf(tmax1, fmaxf(sacc[nt][0], sacc[nt][1]));
            tmax2 = fmaxf(tmax2, fmaxf(sacc[nt][2], sacc[nt][3]));
        }
        tmax1 = fmaxf(tmax1, __shfl_xor_sync(0xffffffffu, tmax1, 1));
        tmax1 = fmaxf(tmax1, __shfl_xor_sync(0xffffffffu, tmax1, 2));
        tmax2 = fmaxf(tmax2, __shfl_xor_sync(0xffffffffu, tmax2, 1));
        tmax2 = fmaxf(tmax2, __shfl_xor_sync(0xffffffffu, tmax2, 2));

        float mn1 = fmaxf(m1, tmax1*SCL2), mn2 = fmaxf(m2, tmax2*SCL2);
        float corr1 = exp2f(m1 - mn1), corr2 = exp2f(m2 - mn2);
        float rs1 = 0.f, rs2 = 0.f;
        #pragma unroll
        for (int nt = 0; nt < 8; ++nt) {
            sacc[nt][0] = exp2f(sacc[nt][0]*SCL2 - mn1);
            sacc[nt][1] = exp2f(sacc[nt][1]*SCL2 - mn1);
            sacc[nt][2] = exp2f(sacc[nt][2]*SCL2 - mn2);
            sacc[nt][3] = exp2f(sacc[nt][3]*SCL2 - mn2);
            rs1 += sacc[nt][0] + sacc[nt][1];
            rs2 += sacc[nt][2] + sacc[nt][3];
        }
        rs1 += __shfl_xor_sync(0xffffffffu, rs1, 1);
        rs1 += __shfl_xor_sync(0xffffffffu, rs1, 2);
        rs2 += __shfl_xor_sync(0xffffffffu, rs2, 1);
        rs2 += __shfl_xor_sync(0xffffffffu, rs2, 2);
        l1 = l1*corr1 + rs1;
        l2 = l2*corr2 + rs2;
        #pragma unroll
        for (int nt = 0; nt < 8; ++nt) {
            oacc[nt][0] *= corr1; oacc[nt][1] *= corr1;
            oacc[nt][2] *= corr2; oacc[nt][3] *= corr2;
        }
        m1 = mn1; m2 = mn2;

        #pragma unroll
        for (int ks = 0; ks < 4; ++ks) {
            unsigned a[4];
            a[0] = packh2(sacc[2*ks][0],   sacc[2*ks][1]);
            a[1] = packh2(sacc[2*ks][2],   sacc[2*ks][3]);
            a[2] = packh2(sacc[2*ks+1][0], sacc[2*ks+1][1]);
            a[3] = packh2(sacc[2*ks+1][2], sacc[2*ks+1][3]);
            #pragma unroll
            for (int ntp = 0; ntp < 4; ++ntp) {
                unsigned vb[4];
                ldsm_x4_t(vb, sptr(&Vc[(ks*16 + l15)*72 + ntp*16 + lhi8]));
                mmah(oacc[2*ntp],   a, vb);
                mmah(oacc[2*ntp+1], a, vb + 2);
            }
        }
        cur ^= 1;
    }

    __syncthreads();
    const float* Mg = M_in + (size_t)bh*DH*DH;
    __half* Mh = KH;
    for (int i = tid; i < DH*DH; i += 256) {
        int d = i >> 6, v = i & 63;
        Mh[d*72 + v] = __float2half_rn(Mg[i]);
    }
    if (tid < DH) Zs[tid] = Z_in[bh*DH + tid];
    __syncthreads();

    float macc[8][4];
    #pragma unroll
    for (int i = 0; i < 8; i++) { macc[i][0]=0.f; macc[i][1]=0.f; macc[i][2]=0.f; macc[i][3]=0.f; }
    float den1 = 0.f, den2 = 0.f;

    #pragma unroll
    for (int ks = 0; ks < 4; ++ks) {
        unsigned a[4];
        int c0 = ks*16 + 2*lc;
        float2 f0 = __half22float2(*(__half2*)&qa[ks][0]);
        float2 f1 = __half22float2(*(__half2*)&qa[ks][1]);
        float2 f2 = __half22float2(*(__half2*)&qa[ks][2]);
        float2 f3 = __half22float2(*(__half2*)&qa[ks][3]);
        float s00 = sigma_f(f0.x), s01 = sigma_f(f0.y);
        float s10 = sigma_f(f1.x), s11 = sigma_f(f1.y);
        float s20 = sigma_f(f2.x), s21 = sigma_f(f2.y);
        float s30 = sigma_f(f3.x), s31 = sigma_f(f3.y);
        a[0] = packh2(s00, s01); a[1] = packh2(s10, s11);
        a[2] = packh2(s20, s21); a[3] = packh2(s30, s31);
        den1 += s00*Zs[c0] + s01*Zs[c0+1] + s20*Zs[c0+8] + s21*Zs[c0+9];
        den2 += s10*Zs[c0] + s11*Zs[c0+1] + s30*Zs[c0+8] + s31*Zs[c0+9];
        #pragma unroll
        for (int ntp = 0; ntp < 4; ++ntp) {
            unsigned mb[4];
            ldsm_x4_t(mb, sptr(&Mh[(ks*16 + l15)*72 + ntp*16 + lhi8]));
            mmah(macc[2*ntp],   a, mb);
            mmah(macc[2*ntp+1], a, mb + 2);
        }
    }
    den1 += __shfl_xor_sync(0xffffffffu, den1, 1);
    den1 += __shfl_xor_sync(0xffffffffu, den1, 2);
    den2 += __shfl_xor_sync(0xffffffffu, den2, 1);
    den2 += __shfl_xor_sync(0xffffffffu, den2, 2);

    float g = 1.f / (1.f + __expf(-beta_gate[h]));
    float iv1 = 1.f/l1, iv2 = 1.f/l2, id1 = 1.f/den1, id2 = 1.f/den2;

    int n1 = qb + rowA;
    float* o1 = outA + ((size_t)(b*NQ + n1))*INNER + h*DH;
    float* o2 = o1 + (size_t)8*INNER;
    #pragma unroll
    for (int nt = 0; nt < 8; ++nt) {
        int d = nt*8 + 2*lc;
        *(float2*)&o1[d] = make_float2(
            g*macc[nt][0]*id1 + (1.f-g)*oacc[nt][0]*iv1,
            g*macc[nt][1]*id1 + (1.f-g)*oacc[nt][1]*iv1);
        *(float2*)&o2[d] = make_float2(
            g*macc[nt][2]*id2 + (1.f-g)*oacc[nt][2]*iv2,
            g*macc[nt][3]*id2 + (1.f-g)*oacc[nt][3]*iv2);
    }
}

// ---------------------------------------------------------------------------
// Kernel 3a: state partials via tf32 mma, fp16 inputs, SPLIT=8
// ---------------------------------------------------------------------------
#define ST_SMEM_WORDS (4*64*68 + 128)
#define ST_SMEM_BYTES (ST_SMEM_WORDS*4)

__global__ __launch_bounds__(256)
void state_part(const float* __restrict__ M_in, const float* __restrict__ Z_in) {
    extern __shared__ float ssm[];
    unsigned* Sks = (unsigned*)ssm;
    float*    Vs  = ssm + 64*68;
    unsigned* DVt = (unsigned*)(ssm + 2*64*68);
    unsigned* Mt  = (unsigned*)(ssm + 3*64*68);
    float*    Zs  = ssm + 4*64*68;
    float*    invden = Zs + 64;

    const int tid = threadIdx.x, wid = tid >> 5, lane = tid & 31;
    const int lr = lane >> 2, lc = lane & 3;
    const int bh = blockIdx.x >> 3;
    const int chunk = blockIdx.x & 7;
    const int nrows = NQ / SPLIT;
    const int rt = wid & 3, ct = wid >> 2;

    const float* Mg = M_in + (size_t)bh*DH*DH;
    for (int i = tid; i < DH*DH; i += 256) {
        int d = i >> 6, v = i & 63;
        Mt[v*68 + d] = f2tf(Mg[i]);
    }
    if (tid < DH) Zs[tid] = Z_in[bh*DH + tid];

    const __half* kg = g_kh + ((size_t)bh*NQ + (size_t)chunk*nrows)*DH;
    const __half* vg = g_vh + ((size_t)bh*NQ + (size_t)chunk*nrows)*DH;

    float macc[4][4];
    #pragma unroll
    for (int i = 0; i < 4; i++) { macc[i][0]=0.f; macc[i][1]=0.f; macc[i][2]=0.f; macc[i][3]=0.f; }
    float zpart = 0.f;
    const int dz = wid*8 + lr;

    for (int n0 = 0; n0 < nrows; n0 += 64) {
        __syncthreads();
        #pragma unroll
        for (int t = 0; t < 4; ++t) {
            int idx = tid + 256*t;
            int r = idx >> 4, c4 = (idx & 15) << 2;
            __half2 k01 = *(const __half2*)&kg[(size_t)(n0+r)*DH + c4];
            __half2 k23 = *(const __half2*)&kg[(size_t)(n0+r)*DH + c4 + 2];
            float2 ka = __half22float2(k01), kb = __half22float2(k23);
            ka.x = sigma_f(ka.x); ka.y = sigma_f(ka.y);
            kb.x = sigma_f(kb.x); kb.y = sigma_f(kb.y);
            *(uint4*)&Sks[r*68 + c4] = make_uint4(f2tf(ka.x), f2tf(ka.y), f2tf(kb.x), f2tf(kb.y));
            __half2 v01 = *(const __half2*)&vg[(size_t)(n0+r)*DH + c4];
            __half2 v23 = *(const __half2*)&vg[(size_t)(n0+r)*DH + c4 + 2];
            float2 va = __half22float2(v01), vb = __half22float2(v23);
            *(float4*)&Vs[r*68 + c4] = make_float4(va.x, va.y, vb.x, vb.y);
        }
        __syncthreads();

        {
            int rn = wid*8 + lr;
            float acc = 0.f;
            #pragma unroll
            for (int j = 0; j < 16; ++j) {
                int d = lc*16 + j;
                acc += __uint_as_float(Sks[rn*68 + d]) * Zs[d];
            }
            acc += __shfl_xor_sync(0xffffffffu, acc, 1);
            acc += __shfl_xor_sync(0xffffffffu, acc, 2);
            if (lc == 0) invden[rn] = 1.f / acc;
            #pragma unroll
            for (int j = 0; j < 16; ++j)
                zpart += __uint_as_float(Sks[(lc*16 + j)*68 + dz]);
        }
        __syncthreads();

        float pacc[4][4];
        #pragma unroll
        for (int i = 0; i < 4; i++) { pacc[i][0]=0.f; pacc[i][1]=0.f; pacc[i][2]=0.f; pacc[i][3]=0.f; }
        #pragma unroll
        for (int ks = 0; ks < 8; ++ks) {
            unsigned a[4];
            a[0] = Sks[(rt*16+lr)*68 + ks*8+lc];
            a[1] = Sks[(rt*16+lr+8)*68 + ks*8+lc];
            a[2] = Sks[(rt*16+lr)*68 + ks*8+lc+4];
            a[3] = Sks[(rt*16+lr+8)*68 + ks*8+lc+4];
            #pragma unroll
            for (int nt = 0; nt < 4; ++nt) {
                unsigned bf[2];
                bf[0] = Mt[(ct*32+nt*8+lr)*68 + ks*8+lc];
                bf[1] = Mt[(ct*32+nt*8+lr)*68 + ks*8+lc+4];
                mma8(pacc[nt], a, bf);
            }
        }

        {
            int r0 = rt*16 + lr, r1 = r0 + 8;
            float iv0 = invden[r0], iv1 = invden[r1];
            #pragma unroll
            for (int nt = 0; nt < 4; ++nt) {
                int c0 = ct*32 + nt*8 + 2*lc, c1 = c0 + 1;
                DVt[c0*68 + r0] = f2tf(Vs[r0*68 + c0] - pacc[nt][0]*iv0);
                DVt[c1*68 + r0] = f2tf(Vs[r0*68 + c1] - pacc[nt][1]*iv0);
                DVt[c0*68 + r1] = f2tf(Vs[r1*68 + c0] - pacc[nt][2]*iv1);
                DVt[c1*68 + r1] = f2tf(Vs[r1*68 + c1] - pacc[nt][3]*iv1);
            }
        }
        __syncthreads();

        #pragma unroll
        for (int ks = 0; ks < 8; ++ks) {
            unsigned a[4];
            a[0] = Sks[(ks*8+lc)*68 + rt*16+lr];
            a[1] = Sks[(ks*8+lc)*68 + rt*16+lr+8];
            a[2] = Sks[(ks*8+lc+4)*68 + rt*16+lr];
            a[3] = Sks[(ks*8+lc+4)*68 + rt*16+lr+8];
            #pragma unroll
            for (int nt = 0; nt < 4; ++nt) {
                unsigned bf[2];
                bf[0] = DVt[(ct*32+nt*8+lr)*68 + ks*8+lc];
                bf[1] = DVt[(ct*32+nt*8+lr)*68 + ks*8+lc+4];
                mma8(macc[nt], a, bf);
            }
        }
    }

    float* mp = g_mpart + (size_t)blockIdx.x * DH*DH;
    int d0 = rt*16 + lr, d1 = d0 + 8;
    #pragma unroll
    for (int nt = 0; nt < 4; ++nt) {
        int c0 = ct*32 + nt*8 + 2*lc;
        *(float2*)&mp[d0*DH + c0] = make_float2(macc[nt][0], macc[nt][1]);
        *(float2*)&mp[d1*DH + c0] = make_float2(macc[nt][2], macc[nt][3]);
    }
    zpart += __shfl_xor_sync(0xffffffffu, zpart, 1);
    zpart += __shfl_xor_sync(0xffffffffu, zpart, 2);
    if (lc == 0) g_zpart[blockIdx.x*DH + dz] = zpart;
}

// ---------------------------------------------------------------------------
// Kernel 3b: reduce 8 partials -> out
// ---------------------------------------------------------------------------
__global__ __launch_bounds__(256)
void state_reduce(const float* __restrict__ M_in, const float* __restrict__ Z_in,
                  const float* __restrict__ beta_lin, float* __restrict__ out) {
    const int bh = blockIdx.x;
    const int tid = threadIdx.x;
    float beta = 1.f / (1.f + __expf(-beta_lin[0]));
    beta = fminf(fmaxf(beta, 0.9f), 0.999f);

    const float* Mg = M_in + (size_t)bh*DH*DH;
    float* mo = out + A_ELEMS + (size_t)bh*DH*DH;
    for (int e = tid; e < DH*DH; e += 256) {
        float s = beta*Mg[e];
        #pragma unroll
        for (int c = 0; c < SPLIT; ++c)
            s += g_mpart[(size_t)(bh*SPLIT + c)*DH*DH + e];
        mo[e] = s;
    }
    if (tid < DH) {
        float z = 0.f;
        #pragma unroll
        for (int c = 0; c < SPLIT; ++c)
            z += g_zpart[(bh*SPLIT + c)*DH + tid];
        out[A_ELEMS + M_ELEMS + bh*DH + tid] = beta*Z_in[bh*DH + tid] + z;
    }
}

// ---------------------------------------------------------------------------
extern "C" void kernel_launch(void* const* d_in, const int* in_sizes, int n_in,
                              void* d_out, int out_size) {
    const float* x         = (const float*)d_in[0];
    const float* M         = (const float*)d_in[1];
    const float* Z         = (const float*)d_in[2];
    const float* W         = (const float*)d_in[3];
    const float* beta_lin  = (const float*)d_in[4];
    const float* beta_gate = (const float*)d_in[5];
    float* out = (float*)d_out;

    cudaFuncSetAttribute(qkv_gemm, cudaFuncAttributeMaxDynamicSharedMemorySize, QKV_SMEM_BYTES);
    cudaFuncSetAttribute(attn_k, cudaFuncAttributeMaxDynamicSharedMemorySize, ATT_SMEM_BYTES);
    cudaFuncSetAttribute(state_part, cudaFuncAttributeMaxDynamicSharedMemorySize, ST_SMEM_BYTES);

    const int npc = (BB*NQ*DIMK + DIMK*NCOLS)/4;
    preconv<<<(npc + 255)/256, 256>>>(x, W);
    qkv_gemm<<<dim3(NCOLS/128, (BB*NQ)/128), 256, QKV_SMEM_BYTES>>>();
    attn_k<<<dim3(NQ/128, HEADS, BB), 256, ATT_SMEM_BYTES>>>(M, Z, beta_gate, out);
    state_part<<<BB*HEADS*SPLIT, 256, ST_SMEM_BYTES>>>(M, Z);
    state_reduce<<<BB*HEADS, 256>>>(M, Z, beta_lin, out);
}

// round 9
// speedup vs baseline: 2.7996x; 1.0680x over previous
#include <cuda_runtime.h>
#include <cuda_fp16.h>

#define BB    4
#define NQ    2048
#define DIMK  1024
#define HEADS 16
#define DH    64
#define INNER 1024
#define NCOLS 3072
#define SPLIT 4

#define A_ELEMS (BB*NQ*INNER)
#define M_ELEMS (BB*HEADS*DH*DH)

__device__ __half g_qh[BB*HEADS*NQ*DH];
__device__ __half g_kh[BB*HEADS*NQ*DH];
__device__ __half g_vh[BB*HEADS*NQ*DH];
__device__ __half g_xh[BB*NQ*DIMK];
__device__ __half g_wh[DIMK*NCOLS];
__device__ float  g_mpart[BB*HEADS*SPLIT*DH*DH];
__device__ float  g_zpart[BB*HEADS*SPLIT*DH];

__device__ __forceinline__ unsigned f2tf(float f) {
    unsigned u; asm("cvt.rna.tf32.f32 %0, %1;" : "=r"(u) : "f"(f)); return u;
}
__device__ __forceinline__ void mma8(float* c, const unsigned* a, const unsigned* b) {
    asm volatile(
        "mma.sync.aligned.m16n8k8.row.col.f32.tf32.tf32.f32 "
        "{%0,%1,%2,%3}, {%4,%5,%6,%7}, {%8,%9}, {%0,%1,%2,%3};\n"
        : "+f"(c[0]), "+f"(c[1]), "+f"(c[2]), "+f"(c[3])
        : "r"(a[0]), "r"(a[1]), "r"(a[2]), "r"(a[3]), "r"(b[0]), "r"(b[1]));
}
__device__ __forceinline__ void mmah(float* c, const unsigned* a, const unsigned* b) {
    asm volatile(
        "mma.sync.aligned.m16n8k16.row.col.f32.f16.f16.f32 "
        "{%0,%1,%2,%3}, {%4,%5,%6,%7}, {%8,%9}, {%0,%1,%2,%3};\n"
        : "+f"(c[0]), "+f"(c[1]), "+f"(c[2]), "+f"(c[3])
        : "r"(a[0]), "r"(a[1]), "r"(a[2]), "r"(a[3]), "r"(b[0]), "r"(b[1]));
}
__device__ __forceinline__ void ldsm_x4(unsigned* r, unsigned addr) {
    asm volatile("ldmatrix.sync.aligned.m8n8.x4.shared.b16 {%0,%1,%2,%3}, [%4];"
        : "=r"(r[0]), "=r"(r[1]), "=r"(r[2]), "=r"(r[3]) : "r"(addr));
}
__device__ __forceinline__ void ldsm_x4_t(unsigned* r, unsigned addr) {
    asm volatile("ldmatrix.sync.aligned.m8n8.x4.trans.shared.b16 {%0,%1,%2,%3}, [%4];"
        : "=r"(r[0]), "=r"(r[1]), "=r"(r[2]), "=r"(r[3]) : "r"(addr));
}
__device__ __forceinline__ void ldsm_x2_t(unsigned* r, unsigned addr) {
    asm volatile("ldmatrix.sync.aligned.m8n8.x2.trans.shared.b16 {%0,%1}, [%2];"
        : "=r"(r[0]), "=r"(r[1]) : "r"(addr));
}
__device__ __forceinline__ unsigned packh2(float a, float b) {
    __half2 h = __floats2half2_rn(a, b);
    return *(unsigned*)&h;
}
// exp2 of two floats, result as packed halves (fp16 MUFU approx)
__device__ __forceinline__ unsigned ex2h2(float a, float b) {
    unsigned p = packh2(a, b);
    unsigned r; asm("ex2.approx.f16x2 %0, %1;" : "=r"(r) : "r"(p));
    return r;
}
__device__ __forceinline__ float sigma_f(float f) {
    return (f > 0.f) ? (f + 1.f) : __expf(f);
}
__device__ __forceinline__ unsigned sptr(const void* p) {
    return (unsigned)__cvta_generic_to_shared(p);
}
#define CP16(dst, src) asm volatile("cp.async.ca.shared.global [%0], [%1], 16;" :: "r"(dst), "l"(src))
#define CP_COMMIT()    asm volatile("cp.async.commit_group;")
#define CP_WAIT0()     asm volatile("cp.async.wait_group 0;")
#define CP_WAIT1()     asm volatile("cp.async.wait_group 1;")

// ---------------------------------------------------------------------------
// Kernel 0: x, W -> half
// ---------------------------------------------------------------------------
__global__ __launch_bounds__(256)
void preconv(const float* __restrict__ x, const float* __restrict__ W) {
    const int nx = BB*NQ*DIMK/4;
    const int nw = DIMK*NCOLS/4;
    int i = blockIdx.x*256 + threadIdx.x;
    if (i < nx) {
        float4 v = ((const float4*)x)[i];
        ((__half2*)g_xh)[2*i]   = __floats2half2_rn(v.x, v.y);
        ((__half2*)g_xh)[2*i+1] = __floats2half2_rn(v.z, v.w);
    } else if (i < nx + nw) {
        int j = i - nx;
        float4 v = ((const float4*)W)[j];
        ((__half2*)g_wh)[2*j]   = __floats2half2_rn(v.x, v.y);
        ((__half2*)g_wh)[2*j+1] = __floats2half2_rn(v.z, v.w);
    }
}

// ---------------------------------------------------------------------------
// Kernel 1: QKV GEMM fp16 mma, BK=32, 3-stage cp.async pipeline
// ---------------------------------------------------------------------------
#define QA_STG (128*40)
#define QB_STG (32*136)
#define QKV_SMEM_BYTES ((3*QA_STG + 3*QB_STG)*2)

__global__ __launch_bounds__(256, 2)
void qkv_gemm(void) {
    extern __shared__ __align__(16) __half qsm[];
    __half* As = qsm;
    __half* Bs = qsm + 3*QA_STG;

    const int tid  = threadIdx.x;
    const int bm   = blockIdx.y * 128, bn = blockIdx.x * 128;
    const int wid  = tid >> 5, lane = tid & 31;
    const int wm   = (wid & 1) * 64, wn = (wid >> 1) * 32;
    const int lr   = lane >> 2, lc = lane & 3;

    const int ar = tid >> 2, ach = tid & 3;
    const int br = tid >> 4, bch = tid & 15;
    const __half* asrc0 = g_xh + (size_t)(bm + ar) * DIMK + ach*8;
    const __half* asrc1 = asrc0 + (size_t)64 * DIMK;
    const __half* bsrc0 = g_wh + (size_t)br * NCOLS + bn + bch*8;
    const __half* bsrc1 = bsrc0 + (size_t)16 * NCOLS;
    const unsigned a_off = sptr(&As[ar*40 + ach*8]);
    const unsigned b_off = sptr(&Bs[br*136 + bch*8]);

    #pragma unroll
    for (int s = 0; s < 2; ++s) {
        int ko = s * 32;
        CP16(a_off + s*QA_STG*2, asrc0 + ko);
        CP16(a_off + s*QA_STG*2 + 64*40*2, asrc1 + ko);
        CP16(b_off + s*QB_STG*2, bsrc0 + (size_t)ko * NCOLS);
        CP16(b_off + s*QB_STG*2 + 16*136*2, bsrc1 + (size_t)ko * NCOLS);
        CP_COMMIT();
    }

    float cacc[4][4][4];
    #pragma unroll
    for (int i = 0; i < 4; i++)
        #pragma unroll
        for (int j = 0; j < 4; j++) { cacc[i][j][0]=0.f; cacc[i][j][1]=0.f; cacc[i][j][2]=0.f; cacc[i][j][3]=0.f; }

    const int l15 = lane & 15;
    const int lhi8 = (lane & 16) >> 1;
    int cur = 0;
    for (int kt = 0; kt < DIMK/32; ++kt) {
        CP_WAIT1();
        __syncthreads();
        if (kt + 2 < DIMK/32) {
            int ko = (kt + 2) * 32;
            int nxs = (cur + 2) % 3;
            CP16(a_off + nxs*QA_STG*2, asrc0 + ko);
            CP16(a_off + nxs*QA_STG*2 + 64*40*2, asrc1 + ko);
            CP16(b_off + nxs*QB_STG*2, bsrc0 + (size_t)ko * NCOLS);
            CP16(b_off + nxs*QB_STG*2 + 16*136*2, bsrc1 + (size_t)ko * NCOLS);
            CP_COMMIT();
        }

        const __half* Ah = As + cur*QA_STG;
        const __half* Bh = Bs + cur*QB_STG;
        #pragma unroll
        for (int ks = 0; ks < 2; ++ks) {
            unsigned af[4][4];
            #pragma unroll
            for (int mt = 0; mt < 4; ++mt)
                ldsm_x4(af[mt], sptr(&Ah[(wm + mt*16 + l15)*40 + ks*16 + lhi8]));
            #pragma unroll
            for (int ntp = 0; ntp < 2; ++ntp) {
                unsigned bf[4];
                ldsm_x4_t(bf, sptr(&Bh[(ks*16 + l15)*136 + wn + ntp*16 + lhi8]));
                #pragma unroll
                for (int mt = 0; mt < 4; ++mt) {
                    mmah(cacc[mt][2*ntp],   af[mt], bf);
                    mmah(cacc[mt][2*ntp+1], af[mt], bf + 2);
                }
            }
        }
        cur = (cur + 1) % 3;
    }

    const int part = (bn + wn) >> 10;
    __half* dst = (part == 0) ? g_qh : (part == 1) ? g_kh : g_vh;
    #pragma unroll
    for (int mt = 0; mt < 4; ++mt) {
        int r0 = bm + wm + mt*16 + lr;
        #pragma unroll
        for (int nt = 0; nt < 4; ++nt) {
            int cg = bn + wn + nt*8 + 2*lc;
            int hh = (cg >> 6) & (HEADS - 1);
            int dd = cg & 63;
            int bi = r0 >> 11, nn = r0 & 2047;
            size_t off = (((size_t)(bi*HEADS + hh) * NQ + nn) * DH) + dd;
            int r1 = r0 + 8;
            int bi1 = r1 >> 11, nn1 = r1 & 2047;
            size_t off2 = (((size_t)(bi1*HEADS + hh) * NQ + nn1) * DH) + dd;
            *(unsigned*)&dst[off]  = packh2(cacc[mt][nt][0], cacc[mt][nt][1]);
            *(unsigned*)&dst[off2] = packh2(cacc[mt][nt][2], cacc[mt][nt][3]);
        }
    }
}

// ---------------------------------------------------------------------------
// Kernel 2: fp16 flash attention, static-shift softmax (no max), mma row-sums.
// smem: KH[2][64*72] | VH[2][64*88] (col64=1 ones column) | Zs[64]
// ---------------------------------------------------------------------------
#define KTK (64*72)
#define KTV (64*88)
#define ATT_SMEM_BYTES ((2*KTK + 2*KTV)*2 + 64*4)
#define SCL2 0.1803368801111204f   // 0.125 * log2(e)

__global__ __launch_bounds__(256, 2)
void attn_k(const float* __restrict__ M_in, const float* __restrict__ Z_in,
            const float* __restrict__ beta_gate, float* __restrict__ outA) {
    extern __shared__ __align__(16) __half smh[];
    __half* KH = smh;
    __half* VH = smh + 2*KTK;
    float*  Zs = (float*)(smh + 2*KTK + 2*KTV);

    const int tid = threadIdx.x, wid = tid >> 5, lane = tid & 31;
    const int lr = lane >> 2, lc = lane & 3;
    const int l15 = lane & 15;
    const int l7  = lane & 7;
    const int lhi8 = (lane & 16) >> 1;
    const int b = blockIdx.z, h = blockIdx.y, bh = b*HEADS + h;
    const int qb = blockIdx.x * 128;
    const int rowA = wid*16 + lr;

    const __half* qg = g_qh + ((size_t)bh*NQ + qb)*DH;
    const __half* kg = g_kh + (size_t)bh*NQ*DH;
    const __half* vg = g_vh + (size_t)bh*NQ*DH;

    const int cr = tid >> 3, cch = tid & 7;
    const unsigned k_off = sptr(&KH[cr*72 + cch*8]);
    const unsigned v_off = sptr(&VH[cr*88 + cch*8]);
    const __half* ksrc = kg + (size_t)cr*DH + cch*8;
    const __half* vsrc = vg + (size_t)cr*DH + cch*8;
    #define KROW32 (32*72*2)
    #define VROW32 (32*88*2)

    // init ones-column region (cols 64..71) of both V buffers
    for (int i = tid; i < 128; i += 256) {
        int buf = i >> 6, r = i & 63;
        __half* vrow = VH + buf*KTV + r*88 + 64;
        vrow[0] = __float2half(1.f);
        #pragma unroll
        for (int c = 1; c < 8; ++c) vrow[c] = __float2half(0.f);
    }

    unsigned qa[4][4];
    #pragma unroll
    for (int ks = 0; ks < 4; ++ks) {
        qa[ks][0] = *(const unsigned*)&qg[(size_t)rowA*DH + ks*16 + 2*lc];
        qa[ks][1] = *(const unsigned*)&qg[(size_t)(rowA+8)*DH + ks*16 + 2*lc];
        qa[ks][2] = *(const unsigned*)&qg[(size_t)rowA*DH + ks*16 + 2*lc + 8];
        qa[ks][3] = *(const unsigned*)&qg[(size_t)(rowA+8)*DH + ks*16 + 2*lc + 8];
    }

    CP16(k_off, ksrc); CP16(k_off + KROW32, ksrc + 32*DH);
    CP16(v_off, vsrc); CP16(v_off + VROW32, vsrc + 32*DH);
    CP_COMMIT();

    float oacc[8][4];
    #pragma unroll
    for (int i = 0; i < 8; i++) { oacc[i][0]=0.f; oacc[i][1]=0.f; oacc[i][2]=0.f; oacc[i][3]=0.f; }
    float osum[4] = {0.f, 0.f, 0.f, 0.f};

    int cur = 0;
    for (int jt = 0; jt < NQ; jt += 64) {
        CP_WAIT0();
        __syncthreads();
        if (jt + 64 < NQ) {
            int nx = cur ^ 1;
            const __half* kn = ksrc + (size_t)(jt + 64)*DH;
            const __half* vn = vsrc + (size_t)(jt + 64)*DH;
            CP16(k_off + nx*KTK*2, kn); CP16(k_off + nx*KTK*2 + KROW32, kn + 32*DH);
            CP16(v_off + nx*KTV*2, vn); CP16(v_off + nx*KTV*2 + VROW32, vn + 32*DH);
            CP_COMMIT();
        }
        const __half* Kc = KH + cur*KTK;
        const __half* Vc = VH + cur*KTV;

        // S = Q K^T (raw dots, fp32 accum)
        float sacc[8][4];
        #pragma unroll
        for (int i = 0; i < 8; i++) { sacc[i][0]=0.f; sacc[i][1]=0.f; sacc[i][2]=0.f; sacc[i][3]=0.f; }
        #pragma unroll
        for (int ks = 0; ks < 4; ++ks) {
            #pragma unroll
            for (int ntp = 0; ntp < 4; ++ntp) {
                unsigned kb[4];
                ldsm_x4(kb, sptr(&Kc[(ntp*16 + l7 + lhi8)*72 + ks*16 + (lane & 8)]));
                mmah(sacc[2*ntp],   qa[ks], kb);
                mmah(sacc[2*ntp+1], qa[ks], kb + 2);
            }
        }

        // P = exp2(S*SCL2) straight into half A-fragments; O += P V; l via ones column
        #pragma unroll
        for (int ks = 0; ks < 4; ++ks) {
            unsigned a[4];
            a[0] = ex2h2(sacc[2*ks][0]*SCL2,   sacc[2*ks][1]*SCL2);
            a[1] = ex2h2(sacc[2*ks][2]*SCL2,   sacc[2*ks][3]*SCL2);
            a[2] = ex2h2(sacc[2*ks+1][0]*SCL2, sacc[2*ks+1][1]*SCL2);
            a[3] = ex2h2(sacc[2*ks+1][2]*SCL2, sacc[2*ks+1][3]*SCL2);
            #pragma unroll
            for (int ntp = 0; ntp < 4; ++ntp) {
                unsigned vb[4];
                ldsm_x4_t(vb, sptr(&Vc[(ks*16 + l15)*88 + ntp*16 + lhi8]));
                mmah(oacc[2*ntp],   a, vb);
                mmah(oacc[2*ntp+1], a, vb + 2);
            }
            unsigned vs[2];
            ldsm_x2_t(vs, sptr(&Vc[(ks*16 + l15)*88 + 64]));
            mmah(osum, a, vs);
        }
        cur ^= 1;
    }

    // row sums (col 64) live at lc==0 threads
    float l1 = __shfl_sync(0xffffffffu, osum[0], lane & 28);
    float l2 = __shfl_sync(0xffffffffu, osum[2], lane & 28);

    // epilogue: A_mem = sigma(Q) @ M via fp16 mma
    __syncthreads();
    const float* Mg = M_in + (size_t)bh*DH*DH;
    __half* Mh = KH;
    for (int i = tid; i < DH*DH; i += 256) {
        int d = i >> 6, v = i & 63;
        Mh[d*72 + v] = __float2half_rn(Mg[i]);
    }
    if (tid < DH) Zs[tid] = Z_in[bh*DH + tid];
    __syncthreads();

    float macc[8][4];
    #pragma unroll
    for (int i = 0; i < 8; i++) { macc[i][0]=0.f; macc[i][1]=0.f; macc[i][2]=0.f; macc[i][3]=0.f; }
    float den1 = 0.f, den2 = 0.f;

    #pragma unroll
    for (int ks = 0; ks < 4; ++ks) {
        unsigned a[4];
        int c0 = ks*16 + 2*lc;
        float2 f0 = __half22float2(*(__half2*)&qa[ks][0]);
        float2 f1 = __half22float2(*(__half2*)&qa[ks][1]);
        float2 f2 = __half22float2(*(__half2*)&qa[ks][2]);
        float2 f3 = __half22float2(*(__half2*)&qa[ks][3]);
        float s00 = sigma_f(f0.x), s01 = sigma_f(f0.y);
        float s10 = sigma_f(f1.x), s11 = sigma_f(f1.y);
        float s20 = sigma_f(f2.x), s21 = sigma_f(f2.y);
        float s30 = sigma_f(f3.x), s31 = sigma_f(f3.y);
        a[0] = packh2(s00, s01); a[1] = packh2(s10, s11);
        a[2] = packh2(s20, s21); a[3] = packh2(s30, s31);
        den1 += s00*Zs[c0] + s01*Zs[c0+1] + s20*Zs[c0+8] + s21*Zs[c0+9];
        den2 += s10*Zs[c0] + s11*Zs[c0+1] + s30*Zs[c0+8] + s31*Zs[c0+9];
        #pragma unroll
        for (int ntp = 0; ntp < 4; ++ntp) {
            unsigned mb[4];
            ldsm_x4_t(mb, sptr(&Mh[(ks*16 + l15)*72 + ntp*16 + lhi8]));
            mmah(macc[2*ntp],   a, mb);
            mmah(macc[2*ntp+1], a, mb + 2);
        }
    }
    den1 += __shfl_xor_sync(0xffffffffu, den1, 1);
    den1 += __shfl_xor_sync(0xffffffffu, den1, 2);
    den2 += __shfl_xor_sync(0xffffffffu, den2, 1);
    den2 += __shfl_xor_sync(0xffffffffu, den2, 2);

    float g = 1.f / (1.f + __expf(-beta_gate[h]));
    float iv1 = 1.f/l1, iv2 = 1.f/l2, id1 = 1.f/den1, id2 = 1.f/den2;

    int n1 = qb + rowA;
    float* o1 = outA + ((size_t)(b*NQ + n1))*INNER + h*DH;
    float* o2 = o1 + (size_t)8*INNER;
    #pragma unroll
    for (int nt = 0; nt < 8; ++nt) {
        int d = nt*8 + 2*lc;
        *(float2*)&o1[d] = make_float2(
            g*macc[nt][0]*id1 + (1.f-g)*oacc[nt][0]*iv1,
            g*macc[nt][1]*id1 + (1.f-g)*oacc[nt][1]*iv1);
        *(float2*)&o2[d] = make_float2(
            g*macc[nt][2]*id2 + (1.f-g)*oacc[nt][2]*iv2,
            g*macc[nt][3]*id2 + (1.f-g)*oacc[nt][3]*iv2);
    }
}

// ---------------------------------------------------------------------------
// Kernel 3a: state partials via tf32 mma, fp16 inputs, SPLIT=4
// ---------------------------------------------------------------------------
#define ST_SMEM_WORDS (4*64*68 + 128)
#define ST_SMEM_BYTES (ST_SMEM_WORDS*4)

__global__ __launch_bounds__(256)
void state_part(const float* __restrict__ M_in, const float* __restrict__ Z_in) {
    extern __shared__ float ssm[];
    unsigned* Sks = (unsigned*)ssm;
    float*    Vs  = ssm + 64*68;
    unsigned* DVt = (unsigned*)(ssm + 2*64*68);
    unsigned* Mt  = (unsigned*)(ssm + 3*64*68);
    float*    Zs  = ssm + 4*64*68;
    float*    invden = Zs + 64;

    const int tid = threadIdx.x, wid = tid >> 5, lane = tid & 31;
    const int lr = lane >> 2, lc = lane & 3;
    const int bh = blockIdx.x >> 2;
    const int chunk = blockIdx.x & 3;
    const int nrows = NQ / SPLIT;
    const int rt = wid & 3, ct = wid >> 2;

    const float* Mg = M_in + (size_t)bh*DH*DH;
    for (int i = tid; i < DH*DH; i += 256) {
        int d = i >> 6, v = i & 63;
        Mt[v*68 + d] = f2tf(Mg[i]);
    }
    if (tid < DH) Zs[tid] = Z_in[bh*DH + tid];

    const __half* kg = g_kh + ((size_t)bh*NQ + (size_t)chunk*nrows)*DH;
    const __half* vg = g_vh + ((size_t)bh*NQ + (size_t)chunk*nrows)*DH;

    float macc[4][4];
    #pragma unroll
    for (int i = 0; i < 4; i++) { macc[i][0]=0.f; macc[i][1]=0.f; macc[i][2]=0.f; macc[i][3]=0.f; }
    float zpart = 0.f;
    const int dz = wid*8 + lr;

    for (int n0 = 0; n0 < nrows; n0 += 64) {
        __syncthreads();
        #pragma unroll
        for (int t = 0; t < 4; ++t) {
            int idx = tid + 256*t;
            int r = idx >> 4, c4 = (idx & 15) << 2;
            __half2 k01 = *(const __half2*)&kg[(size_t)(n0+r)*DH + c4];
            __half2 k23 = *(const __half2*)&kg[(size_t)(n0+r)*DH + c4 + 2];
            float2 ka = __half22float2(k01), kb = __half22float2(k23);
            ka.x = sigma_f(ka.x); ka.y = sigma_f(ka.y);
            kb.x = sigma_f(kb.x); kb.y = sigma_f(kb.y);
            *(uint4*)&Sks[r*68 + c4] = make_uint4(f2tf(ka.x), f2tf(ka.y), f2tf(kb.x), f2tf(kb.y));
            __half2 v01 = *(const __half2*)&vg[(size_t)(n0+r)*DH + c4];
            __half2 v23 = *(const __half2*)&vg[(size_t)(n0+r)*DH + c4 + 2];
            float2 va = __half22float2(v01), vb = __half22float2(v23);
            *(float4*)&Vs[r*68 + c4] = make_float4(va.x, va.y, vb.x, vb.y);
        }
        __syncthreads();

        {
            int rn = wid*8 + lr;
            float acc = 0.f;
            #pragma unroll
            for (int j = 0; j < 16; ++j) {
                int d = lc*16 + j;
                acc += __uint_as_float(Sks[rn*68 + d]) * Zs[d];
            }
            acc += __shfl_xor_sync(0xffffffffu, acc, 1);
            acc += __shfl_xor_sync(0xffffffffu, acc, 2);
            if (lc == 0) invden[rn] = 1.f / acc;
            #pragma unroll
            for (int j = 0; j < 16; ++j)
                zpart += __uint_as_float(Sks[(lc*16 + j)*68 + dz]);
        }
        __syncthreads();

        float pacc[4][4];
        #pragma unroll
        for (int i = 0; i < 4; i++) { pacc[i][0]=0.f; pacc[i][1]=0.f; pacc[i][2]=0.f; pacc[i][3]=0.f; }
        #pragma unroll
        for (int ks = 0; ks < 8; ++ks) {
            unsigned a[4];
            a[0] = Sks[(rt*16+lr)*68 + ks*8+lc];
            a[1] = Sks[(rt*16+lr+8)*68 + ks*8+lc];
            a[2] = Sks[(rt*16+lr)*68 + ks*8+lc+4];
            a[3] = Sks[(rt*16+lr+8)*68 + ks*8+lc+4];
            #pragma unroll
            for (int nt = 0; nt < 4; ++nt) {
                unsigned bf[2];
                bf[0] = Mt[(ct*32+nt*8+lr)*68 + ks*8+lc];
                bf[1] = Mt[(ct*32+nt*8+lr)*68 + ks*8+lc+4];
                mma8(pacc[nt], a, bf);
            }
        }

        {
            int r0 = rt*16 + lr, r1 = r0 + 8;
            float iv0 = invden[r0], iv1 = invden[r1];
            #pragma unroll
            for (int nt = 0; nt < 4; ++nt) {
                int c0 = ct*32 + nt*8 + 2*lc, c1 = c0 + 1;
                DVt[c0*68 + r0] = f2tf(Vs[r0*68 + c0] - pacc[nt][0]*iv0);
                DVt[c1*68 + r0] = f2tf(Vs[r0*68 + c1] - pacc[nt][1]*iv0);
                DVt[c0*68 + r1] = f2tf(Vs[r1*68 + c0] - pacc[nt][2]*iv1);
                DVt[c1*68 + r1] = f2tf(Vs[r1*68 + c1] - pacc[nt][3]*iv1);
            }
        }
        __syncthreads();

        #pragma unroll
        for (int ks = 0; ks < 8; ++ks) {
            unsigned a[4];
            a[0] = Sks[(ks*8+lc)*68 + rt*16+lr];
            a[1] = Sks[(ks*8+lc)*68 + rt*16+lr+8];
            a[2] = Sks[(ks*8+lc+4)*68 + rt*16+lr];
            a[3] = Sks[(ks*8+lc+4)*68 + rt*16+lr+8];
            #pragma unroll
            for (int nt = 0; nt < 4; ++nt) {
                unsigned bf[2];
                bf[0] = DVt[(ct*32+nt*8+lr)*68 + ks*8+lc];
                bf[1] = DVt[(ct*32+nt*8+lr)*68 + ks*8+lc+4];
                mma8(macc[nt], a, bf);
            }
        }
    }

    float* mp = g_mpart + (size_t)blockIdx.x * DH*DH;
    int d0 = rt*16 + lr, d1 = d0 + 8;
    #pragma unroll
    for (int nt = 0; nt < 4; ++nt) {
        int c0 = ct*32 + nt*8 + 2*lc;
        *(float2*)&mp[d0*DH + c0] = make_float2(macc[nt][0], macc[nt][1]);
        *(float2*)&mp[d1*DH + c0] = make_float2(macc[nt][2], macc[nt][3]);
    }
    zpart += __shfl_xor_sync(0xffffffffu, zpart, 1);
    zpart += __shfl_xor_sync(0xffffffffu, zpart, 2);
    if (lc == 0) g_zpart[blockIdx.x*DH + dz] = zpart;
}

// ---------------------------------------------------------------------------
// Kernel 3b: reduce partials -> out
// ---------------------------------------------------------------------------
__global__ __launch_bounds__(256)
void state_reduce(const float* __restrict__ M_in, const float* __restrict__ Z_in,
                  const float* __restrict__ beta_lin, float* __restrict__ out) {
    const int bh = blockIdx.x;
    const int tid = threadIdx.x;
    float beta = 1.f / (1.f + __expf(-beta_lin[0]));
    beta = fminf(fmaxf(beta, 0.9f), 0.999f);

    const float* Mg = M_in + (size_t)bh*DH*DH;
    float* mo = out + A_ELEMS + (size_t)bh*DH*DH;
    for (int e = tid; e < DH*DH; e += 256) {
        float s = beta*Mg[e];
        #pragma unroll
        for (int c = 0; c < SPLIT; ++c)
            s += g_mpart[(size_t)(bh*SPLIT + c)*DH*DH + e];
        mo[e] = s;
    }
    if (tid < DH) {
        float z = 0.f;
        #pragma unroll
        for (int c = 0; c < SPLIT; ++c)
            z += g_zpart[(bh*SPLIT + c)*DH + tid];
        out[A_ELEMS + M_ELEMS + bh*DH + tid] = beta*Z_in[bh*DH + tid] + z;
    }
}

// ---------------------------------------------------------------------------
extern "C" void kernel_launch(void* const* d_in, const int* in_sizes, int n_in,
                              void* d_out, int out_size) {
    const float* x         = (const float*)d_in[0];
    const float* M         = (const float*)d_in[1];
    const float* Z         = (const float*)d_in[2];
    const float* W         = (const float*)d_in[3];
    const float* beta_lin  = (const float*)d_in[4];
    const float* beta_gate = (const float*)d_in[5];
    float* out = (float*)d_out;

    cudaFuncSetAttribute(qkv_gemm, cudaFuncAttributeMaxDynamicSharedMemorySize, QKV_SMEM_BYTES);
    cudaFuncSetAttribute(attn_k, cudaFuncAttributeMaxDynamicSharedMemorySize, ATT_SMEM_BYTES);
    cudaFuncSetAttribute(state_part, cudaFuncAttributeMaxDynamicSharedMemorySize, ST_SMEM_BYTES);

    const int npc = (BB*NQ*DIMK + DIMK*NCOLS)/4;
    preconv<<<(npc + 255)/256, 256>>>(x, W);
    qkv_gemm<<<dim3(NCOLS/128, (BB*NQ)/128), 256, QKV_SMEM_BYTES>>>();
    attn_k<<<dim3(NQ/128, HEADS, BB), 256, ATT_SMEM_BYTES>>>(M, Z, beta_gate, out);
    state_part<<<BB*HEADS*SPLIT, 256, ST_SMEM_BYTES>>>(M, Z);
    state_reduce<<<BB*HEADS, 256>>>(M, Z, beta_lin, out);
}

// round 10
// speedup vs baseline: 2.9722x; 1.0617x over previous
#include <cuda_runtime.h>
#include <cuda_fp16.h>

#define BB    4
#define NQ    2048
#define DIMK  1024
#define HEADS 16
#define DH    64
#define INNER 1024
#define NCOLS 3072
#define SPLIT 4

#define A_ELEMS (BB*NQ*INNER)
#define M_ELEMS (BB*HEADS*DH*DH)

__device__ __half g_qh[BB*HEADS*NQ*DH];
__device__ __half g_kh[BB*HEADS*NQ*DH];
__device__ __half g_vh[BB*HEADS*NQ*DH];
__device__ __half g_xh[BB*NQ*DIMK];
__device__ __half g_wh[DIMK*NCOLS];
__device__ float  g_mpart[BB*HEADS*SPLIT*DH*DH];
__device__ float  g_zpart[BB*HEADS*SPLIT*DH];
__device__ unsigned g_cnt[BB*HEADS];   // zero-init; atomicInc wraps -> replay-safe

__device__ __forceinline__ void mmah(float* c, const unsigned* a, const unsigned* b) {
    asm volatile(
        "mma.sync.aligned.m16n8k16.row.col.f32.f16.f16.f32 "
        "{%0,%1,%2,%3}, {%4,%5,%6,%7}, {%8,%9}, {%0,%1,%2,%3};\n"
        : "+f"(c[0]), "+f"(c[1]), "+f"(c[2]), "+f"(c[3])
        : "r"(a[0]), "r"(a[1]), "r"(a[2]), "r"(a[3]), "r"(b[0]), "r"(b[1]));
}
__device__ __forceinline__ void ldsm_x4(unsigned* r, unsigned addr) {
    asm volatile("ldmatrix.sync.aligned.m8n8.x4.shared.b16 {%0,%1,%2,%3}, [%4];"
        : "=r"(r[0]), "=r"(r[1]), "=r"(r[2]), "=r"(r[3]) : "r"(addr));
}
__device__ __forceinline__ void ldsm_x4_t(unsigned* r, unsigned addr) {
    asm volatile("ldmatrix.sync.aligned.m8n8.x4.trans.shared.b16 {%0,%1,%2,%3}, [%4];"
        : "=r"(r[0]), "=r"(r[1]), "=r"(r[2]), "=r"(r[3]) : "r"(addr));
}
__device__ __forceinline__ void ldsm_x2_t(unsigned* r, unsigned addr) {
    asm volatile("ldmatrix.sync.aligned.m8n8.x2.trans.shared.b16 {%0,%1}, [%2];"
        : "=r"(r[0]), "=r"(r[1]) : "r"(addr));
}
__device__ __forceinline__ unsigned packh2(float a, float b) {
    __half2 h = __floats2half2_rn(a, b);
    return *(unsigned*)&h;
}
__device__ __forceinline__ unsigned ex2h2(float a, float b) {
    unsigned p = packh2(a, b);
    unsigned r; asm("ex2.approx.f16x2 %0, %1;" : "=r"(r) : "r"(p));
    return r;
}
__device__ __forceinline__ float sigma_f(float f) {
    return (f > 0.f) ? (f + 1.f) : __expf(f);
}
__device__ __forceinline__ unsigned sptr(const void* p) {
    return (unsigned)__cvta_generic_to_shared(p);
}
#define CP16(dst, src) asm volatile("cp.async.ca.shared.global [%0], [%1], 16;" :: "r"(dst), "l"(src))
#define CP_COMMIT()    asm volatile("cp.async.commit_group;")
#define CP_WAIT0()     asm volatile("cp.async.wait_group 0;")
#define CP_WAIT1()     asm volatile("cp.async.wait_group 1;")

// ---------------------------------------------------------------------------
// Kernel 0: x, W -> half
// ---------------------------------------------------------------------------
__global__ __launch_bounds__(256)
void preconv(const float* __restrict__ x, const float* __restrict__ W) {
    const int nx = BB*NQ*DIMK/4;
    const int nw = DIMK*NCOLS/4;
    int i = blockIdx.x*256 + threadIdx.x;
    if (i < nx) {
        float4 v = ((const float4*)x)[i];
        ((__half2*)g_xh)[2*i]   = __floats2half2_rn(v.x, v.y);
        ((__half2*)g_xh)[2*i+1] = __floats2half2_rn(v.z, v.w);
    } else if (i < nx + nw) {
        int j = i - nx;
        float4 v = ((const float4*)W)[j];
        ((__half2*)g_wh)[2*j]   = __floats2half2_rn(v.x, v.y);
        ((__half2*)g_wh)[2*j+1] = __floats2half2_rn(v.z, v.w);
    }
}

// ---------------------------------------------------------------------------
// Kernel 1: QKV GEMM fp16 mma, BK=32, 3-stage cp.async pipeline (unchanged)
// ---------------------------------------------------------------------------
#define QA_STG (128*40)
#define QB_STG (32*136)
#define QKV_SMEM_BYTES ((3*QA_STG + 3*QB_STG)*2)

__global__ __launch_bounds__(256, 2)
void qkv_gemm(void) {
    extern __shared__ __align__(16) __half qsm[];
    __half* As = qsm;
    __half* Bs = qsm + 3*QA_STG;

    const int tid  = threadIdx.x;
    const int bm   = blockIdx.y * 128, bn = blockIdx.x * 128;
    const int wid  = tid >> 5, lane = tid & 31;
    const int wm   = (wid & 1) * 64, wn = (wid >> 1) * 32;
    const int lr   = lane >> 2, lc = lane & 3;

    const int ar = tid >> 2, ach = tid & 3;
    const int br = tid >> 4, bch = tid & 15;
    const __half* asrc0 = g_xh + (size_t)(bm + ar) * DIMK + ach*8;
    const __half* asrc1 = asrc0 + (size_t)64 * DIMK;
    const __half* bsrc0 = g_wh + (size_t)br * NCOLS + bn + bch*8;
    const __half* bsrc1 = bsrc0 + (size_t)16 * NCOLS;
    const unsigned a_off = sptr(&As[ar*40 + ach*8]);
    const unsigned b_off = sptr(&Bs[br*136 + bch*8]);

    #pragma unroll
    for (int s = 0; s < 2; ++s) {
        int ko = s * 32;
        CP16(a_off + s*QA_STG*2, asrc0 + ko);
        CP16(a_off + s*QA_STG*2 + 64*40*2, asrc1 + ko);
        CP16(b_off + s*QB_STG*2, bsrc0 + (size_t)ko * NCOLS);
        CP16(b_off + s*QB_STG*2 + 16*136*2, bsrc1 + (size_t)ko * NCOLS);
        CP_COMMIT();
    }

    float cacc[4][4][4];
    #pragma unroll
    for (int i = 0; i < 4; i++)
        #pragma unroll
        for (int j = 0; j < 4; j++) { cacc[i][j][0]=0.f; cacc[i][j][1]=0.f; cacc[i][j][2]=0.f; cacc[i][j][3]=0.f; }

    const int l15 = lane & 15;
    const int lhi8 = (lane & 16) >> 1;
    int cur = 0;
    for (int kt = 0; kt < DIMK/32; ++kt) {
        CP_WAIT1();
        __syncthreads();
        if (kt + 2 < DIMK/32) {
            int ko = (kt + 2) * 32;
            int nxs = (cur + 2) % 3;
            CP16(a_off + nxs*QA_STG*2, asrc0 + ko);
            CP16(a_off + nxs*QA_STG*2 + 64*40*2, asrc1 + ko);
            CP16(b_off + nxs*QB_STG*2, bsrc0 + (size_t)ko * NCOLS);
            CP16(b_off + nxs*QB_STG*2 + 16*136*2, bsrc1 + (size_t)ko * NCOLS);
            CP_COMMIT();
        }

        const __half* Ah = As + cur*QA_STG;
        const __half* Bh = Bs + cur*QB_STG;
        #pragma unroll
        for (int ks = 0; ks < 2; ++ks) {
            unsigned af[4][4];
            #pragma unroll
            for (int mt = 0; mt < 4; ++mt)
                ldsm_x4(af[mt], sptr(&Ah[(wm + mt*16 + l15)*40 + ks*16 + lhi8]));
            #pragma unroll
            for (int ntp = 0; ntp < 2; ++ntp) {
                unsigned bf[4];
                ldsm_x4_t(bf, sptr(&Bh[(ks*16 + l15)*136 + wn + ntp*16 + lhi8]));
                #pragma unroll
                for (int mt = 0; mt < 4; ++mt) {
                    mmah(cacc[mt][2*ntp],   af[mt], bf);
                    mmah(cacc[mt][2*ntp+1], af[mt], bf + 2);
                }
            }
        }
        cur = (cur + 1) % 3;
    }

    const int part = (bn + wn) >> 10;
    __half* dst = (part == 0) ? g_qh : (part == 1) ? g_kh : g_vh;
    #pragma unroll
    for (int mt = 0; mt < 4; ++mt) {
        int r0 = bm + wm + mt*16 + lr;
        #pragma unroll
        for (int nt = 0; nt < 4; ++nt) {
            int cg = bn + wn + nt*8 + 2*lc;
            int hh = (cg >> 6) & (HEADS - 1);
            int dd = cg & 63;
            int bi = r0 >> 11, nn = r0 & 2047;
            size_t off = (((size_t)(bi*HEADS + hh) * NQ + nn) * DH) + dd;
            int r1 = r0 + 8;
            int bi1 = r1 >> 11, nn1 = r1 & 2047;
            size_t off2 = (((size_t)(bi1*HEADS + hh) * NQ + nn1) * DH) + dd;
            *(unsigned*)&dst[off]  = packh2(cacc[mt][nt][0], cacc[mt][nt][1]);
            *(unsigned*)&dst[off2] = packh2(cacc[mt][nt][2], cacc[mt][nt][3]);
        }
    }
}

// ---------------------------------------------------------------------------
// Kernel 2: fp16 flash attention, static-shift softmax (unchanged from R9)
// ---------------------------------------------------------------------------
#define KTK (64*72)
#define KTV (64*88)
#define ATT_SMEM_BYTES ((2*KTK + 2*KTV)*2 + 64*4)
#define SCL2 0.1803368801111204f

__global__ __launch_bounds__(256, 2)
void attn_k(const float* __restrict__ M_in, const float* __restrict__ Z_in,
            const float* __restrict__ beta_gate, float* __restrict__ outA) {
    extern __shared__ __align__(16) __half smh[];
    __half* KH = smh;
    __half* VH = smh + 2*KTK;
    float*  Zs = (float*)(smh + 2*KTK + 2*KTV);

    const int tid = threadIdx.x, wid = tid >> 5, lane = tid & 31;
    const int lr = lane >> 2, lc = lane & 3;
    const int l15 = lane & 15;
    const int l7  = lane & 7;
    const int lhi8 = (lane & 16) >> 1;
    const int b = blockIdx.z, h = blockIdx.y, bh = b*HEADS + h;
    const int qb = blockIdx.x * 128;
    const int rowA = wid*16 + lr;

    const __half* qg = g_qh + ((size_t)bh*NQ + qb)*DH;
    const __half* kg = g_kh + (size_t)bh*NQ*DH;
    const __half* vg = g_vh + (size_t)bh*NQ*DH;

    const int cr = tid >> 3, cch = tid & 7;
    const unsigned k_off = sptr(&KH[cr*72 + cch*8]);
    const unsigned v_off = sptr(&VH[cr*88 + cch*8]);
    const __half* ksrc = kg + (size_t)cr*DH + cch*8;
    const __half* vsrc = vg + (size_t)cr*DH + cch*8;
    #define KROW32 (32*72*2)
    #define VROW32 (32*88*2)

    for (int i = tid; i < 128; i += 256) {
        int buf = i >> 6, r = i & 63;
        __half* vrow = VH + buf*KTV + r*88 + 64;
        vrow[0] = __float2half(1.f);
        #pragma unroll
        for (int c = 1; c < 8; ++c) vrow[c] = __float2half(0.f);
    }

    unsigned qa[4][4];
    #pragma unroll
    for (int ks = 0; ks < 4; ++ks) {
        qa[ks][0] = *(const unsigned*)&qg[(size_t)rowA*DH + ks*16 + 2*lc];
        qa[ks][1] = *(const unsigned*)&qg[(size_t)(rowA+8)*DH + ks*16 + 2*lc];
        qa[ks][2] = *(const unsigned*)&qg[(size_t)rowA*DH + ks*16 + 2*lc + 8];
        qa[ks][3] = *(const unsigned*)&qg[(size_t)(rowA+8)*DH + ks*16 + 2*lc + 8];
    }

    CP16(k_off, ksrc); CP16(k_off + KROW32, ksrc + 32*DH);
    CP16(v_off, vsrc); CP16(v_off + VROW32, vsrc + 32*DH);
    CP_COMMIT();

    float oacc[8][4];
    #pragma unroll
    for (int i = 0; i < 8; i++) { oacc[i][0]=0.f; oacc[i][1]=0.f; oacc[i][2]=0.f; oacc[i][3]=0.f; }
    float osum[4] = {0.f, 0.f, 0.f, 0.f};

    int cur = 0;
    for (int jt = 0; jt < NQ; jt += 64) {
        CP_WAIT0();
        __syncthreads();
        if (jt + 64 < NQ) {
            int nx = cur ^ 1;
            const __half* kn = ksrc + (size_t)(jt + 64)*DH;
            const __half* vn = vsrc + (size_t)(jt + 64)*DH;
            CP16(k_off + nx*KTK*2, kn); CP16(k_off + nx*KTK*2 + KROW32, kn + 32*DH);
            CP16(v_off + nx*KTV*2, vn); CP16(v_off + nx*KTV*2 + VROW32, vn + 32*DH);
            CP_COMMIT();
        }
        const __half* Kc = KH + cur*KTK;
        const __half* Vc = VH + cur*KTV;

        float sacc[8][4];
        #pragma unroll
        for (int i = 0; i < 8; i++) { sacc[i][0]=0.f; sacc[i][1]=0.f; sacc[i][2]=0.f; sacc[i][3]=0.f; }
        #pragma unroll
        for (int ks = 0; ks < 4; ++ks) {
            #pragma unroll
            for (int ntp = 0; ntp < 4; ++ntp) {
                unsigned kb[4];
                ldsm_x4(kb, sptr(&Kc[(ntp*16 + l7 + lhi8)*72 + ks*16 + (lane & 8)]));
                mmah(sacc[2*ntp],   qa[ks], kb);
                mmah(sacc[2*ntp+1], qa[ks], kb + 2);
            }
        }

        #pragma unroll
        for (int ks = 0; ks < 4; ++ks) {
            unsigned a[4];
            a[0] = ex2h2(sacc[2*ks][0]*SCL2,   sacc[2*ks][1]*SCL2);
            a[1] = ex2h2(sacc[2*ks][2]*SCL2,   sacc[2*ks][3]*SCL2);
            a[2] = ex2h2(sacc[2*ks+1][0]*SCL2, sacc[2*ks+1][1]*SCL2);
            a[3] = ex2h2(sacc[2*ks+1][2]*SCL2, sacc[2*ks+1][3]*SCL2);
            #pragma unroll
            for (int ntp = 0; ntp < 4; ++ntp) {
                unsigned vb[4];
                ldsm_x4_t(vb, sptr(&Vc[(ks*16 + l15)*88 + ntp*16 + lhi8]));
                mmah(oacc[2*ntp],   a, vb);
                mmah(oacc[2*ntp+1], a, vb + 2);
            }
            unsigned vs[2];
            ldsm_x2_t(vs, sptr(&Vc[(ks*16 + l15)*88 + 64]));
            mmah(osum, a, vs);
        }
        cur ^= 1;
    }

    float l1 = __shfl_sync(0xffffffffu, osum[0], lane & 28);
    float l2 = __shfl_sync(0xffffffffu, osum[2], lane & 28);

    __syncthreads();
    const float* Mg = M_in + (size_t)bh*DH*DH;
    __half* Mh = KH;
    for (int i = tid; i < DH*DH; i += 256) {
        int d = i >> 6, v = i & 63;
        Mh[d*72 + v] = __float2half_rn(Mg[i]);
    }
    if (tid < DH) Zs[tid] = Z_in[bh*DH + tid];
    __syncthreads();

    float macc[8][4];
    #pragma unroll
    for (int i = 0; i < 8; i++) { macc[i][0]=0.f; macc[i][1]=0.f; macc[i][2]=0.f; macc[i][3]=0.f; }
    float den1 = 0.f, den2 = 0.f;

    #pragma unroll
    for (int ks = 0; ks < 4; ++ks) {
        unsigned a[4];
        int c0 = ks*16 + 2*lc;
        float2 f0 = __half22float2(*(__half2*)&qa[ks][0]);
        float2 f1 = __half22float2(*(__half2*)&qa[ks][1]);
        float2 f2 = __half22float2(*(__half2*)&qa[ks][2]);
        float2 f3 = __half22float2(*(__half2*)&qa[ks][3]);
        float s00 = sigma_f(f0.x), s01 = sigma_f(f0.y);
        float s10 = sigma_f(f1.x), s11 = sigma_f(f1.y);
        float s20 = sigma_f(f2.x), s21 = sigma_f(f2.y);
        float s30 = sigma_f(f3.x), s31 = sigma_f(f3.y);
        a[0] = packh2(s00, s01); a[1] = packh2(s10, s11);
        a[2] = packh2(s20, s21); a[3] = packh2(s30, s31);
        den1 += s00*Zs[c0] + s01*Zs[c0+1] + s20*Zs[c0+8] + s21*Zs[c0+9];
        den2 += s10*Zs[c0] + s11*Zs[c0+1] + s30*Zs[c0+8] + s31*Zs[c0+9];
        #pragma unroll
        for (int ntp = 0; ntp < 4; ++ntp) {
            unsigned mb[4];
            ldsm_x4_t(mb, sptr(&Mh[(ks*16 + l15)*72 + ntp*16 + lhi8]));
            mmah(macc[2*ntp],   a, mb);
            mmah(macc[2*ntp+1], a, mb + 2);
        }
    }
    den1 += __shfl_xor_sync(0xffffffffu, den1, 1);
    den1 += __shfl_xor_sync(0xffffffffu, den1, 2);
    den2 += __shfl_xor_sync(0xffffffffu, den2, 1);
    den2 += __shfl_xor_sync(0xffffffffu, den2, 2);

    float g = 1.f / (1.f + __expf(-beta_gate[h]));
    float iv1 = 1.f/l1, iv2 = 1.f/l2, id1 = 1.f/den1, id2 = 1.f/den2;

    int n1 = qb + rowA;
    float* o1 = outA + ((size_t)(b*NQ + n1))*INNER + h*DH;
    float* o2 = o1 + (size_t)8*INNER;
    #pragma unroll
    for (int nt = 0; nt < 8; ++nt) {
        int d = nt*8 + 2*lc;
        *(float2*)&o1[d] = make_float2(
            g*macc[nt][0]*id1 + (1.f-g)*oacc[nt][0]*iv1,
            g*macc[nt][1]*id1 + (1.f-g)*oacc[nt][1]*iv1);
        *(float2*)&o2[d] = make_float2(
            g*macc[nt][2]*id2 + (1.f-g)*oacc[nt][2]*iv2,
            g*macc[nt][3]*id2 + (1.f-g)*oacc[nt][3]*iv2);
    }
}

// ---------------------------------------------------------------------------
// Kernel 3: state partials via fp16 mma + fused last-CTA reduction.
// smem: Sksh[64][72] | Vsh[64][72] | Mth[64][72] halfs | Zs[64] invden[64]
// P = sigma(K)@M (fp16 mma), dv = V - P*invden in place (half2),
// Macc += sigma(K)^T @ dv via trans-ldsm A and B.
// ---------------------------------------------------------------------------
#define ST_SMEM_BYTES ((3*64*72)*2 + 128*4)

__global__ __launch_bounds__(256)
void state_part(const float* __restrict__ M_in, const float* __restrict__ Z_in,
                const float* __restrict__ beta_lin, float* __restrict__ out) {
    extern __shared__ __align__(16) __half sst[];
    __half* Sksh = sst;
    __half* Vsh  = sst + 64*72;
    __half* Mth  = sst + 2*64*72;
    float*  Zs   = (float*)(sst + 3*64*72);
    float*  invden = Zs + 64;
    __shared__ unsigned slast;

    const int tid = threadIdx.x, wid = tid >> 5, lane = tid & 31;
    const int lr = lane >> 2, lc = lane & 3;
    const int l15 = lane & 15, l7 = lane & 7;
    const int lhi8 = (lane & 16) >> 1;
    const int bh = blockIdx.x >> 2;
    const int chunk = blockIdx.x & 3;
    const int nrows = NQ / SPLIT;
    const int rt = wid & 3, ct = wid >> 2;

    const float* Mg = M_in + (size_t)bh*DH*DH;
    for (int i = tid; i < DH*DH; i += 256) {
        int d = i >> 6, v = i & 63;
        Mth[v*72 + d] = __float2half_rn(Mg[i]);
    }
    if (tid < DH) Zs[tid] = Z_in[bh*DH + tid];

    const __half* kg = g_kh + ((size_t)bh*NQ + (size_t)chunk*nrows)*DH;
    const __half* vg = g_vh + ((size_t)bh*NQ + (size_t)chunk*nrows)*DH;

    float macc[4][4];
    #pragma unroll
    for (int i = 0; i < 4; i++) { macc[i][0]=0.f; macc[i][1]=0.f; macc[i][2]=0.f; macc[i][3]=0.f; }
    float zpart = 0.f;
    const int dz = wid*8 + lr;

    for (int n0 = 0; n0 < nrows; n0 += 64) {
        __syncthreads();
        #pragma unroll
        for (int t = 0; t < 2; ++t) {
            int c = tid + 256*t;           // 0..511
            int r = c >> 3, s8 = (c & 7) << 3;
            const __half2* kp = (const __half2*)&kg[(size_t)(n0+r)*DH + s8];
            __half2 h2[4];
            #pragma unroll
            for (int u = 0; u < 4; ++u) {
                float2 f = __half22float2(kp[u]);
                h2[u] = __floats2half2_rn(sigma_f(f.x), sigma_f(f.y));
            }
            *(uint4*)&Sksh[r*72 + s8] = *(uint4*)h2;
            *(uint4*)&Vsh[r*72 + s8] = *(const uint4*)&vg[(size_t)(n0+r)*DH + s8];
        }
        __syncthreads();

        // den per row + z accumulation
        {
            int rn = wid*8 + lr;
            float acc = 0.f;
            const __half2* sp = (const __half2*)&Sksh[rn*72 + lc*16];
            #pragma unroll
            for (int j = 0; j < 8; ++j) {
                float2 f = __half22float2(sp[j]);
                acc += f.x*Zs[lc*16 + 2*j] + f.y*Zs[lc*16 + 2*j + 1];
            }
            acc += __shfl_xor_sync(0xffffffffu, acc, 1);
            acc += __shfl_xor_sync(0xffffffffu, acc, 2);
            if (lc == 0) invden[rn] = 1.f / acc;
            #pragma unroll
            for (int j = 0; j < 16; ++j)
                zpart += __half2float(Sksh[(lc*16 + j)*72 + dz]);
        }
        __syncthreads();

        // P = Sk @ M : warp tile rows rt*16..+15, cols ct*32..+31
        float pacc[4][4];
        #pragma unroll
        for (int i = 0; i < 4; i++) { pacc[i][0]=0.f; pacc[i][1]=0.f; pacc[i][2]=0.f; pacc[i][3]=0.f; }
        #pragma unroll
        for (int ks = 0; ks < 4; ++ks) {
            unsigned af[4];
            ldsm_x4(af, sptr(&Sksh[(rt*16 + l15)*72 + ks*16 + lhi8]));
            #pragma unroll
            for (int ntp = 0; ntp < 2; ++ntp) {
                unsigned bf[4];
                ldsm_x4(bf, sptr(&Mth[(ct*32 + ntp*16 + l7 + lhi8)*72 + ks*16 + (lane & 8)]));
                mmah(pacc[2*ntp],   af, bf);
                mmah(pacc[2*ntp+1], af, bf + 2);
            }
        }

        // dv = V - P*invden, in place (half2)
        {
            int r0 = rt*16 + lr, r1 = r0 + 8;
            float iv0 = invden[r0], iv1 = invden[r1];
            #pragma unroll
            for (int nt = 0; nt < 4; ++nt) {
                int c0 = ct*32 + nt*8 + 2*lc;
                float2 fv0 = __half22float2(*(__half2*)&Vsh[r0*72 + c0]);
                *(__half2*)&Vsh[r0*72 + c0] =
                    __floats2half2_rn(fv0.x - pacc[nt][0]*iv0, fv0.y - pacc[nt][1]*iv0);
                float2 fv1 = __half22float2(*(__half2*)&Vsh[r1*72 + c0]);
                *(__half2*)&Vsh[r1*72 + c0] =
                    __floats2half2_rn(fv1.x - pacc[nt][2]*iv1, fv1.y - pacc[nt][3]*iv1);
            }
        }
        __syncthreads();

        // Macc[d][v] += Sk^T @ dv : A via trans-ldsm on Sksh, B via trans-ldsm on Vsh
        #pragma unroll
        for (int ks = 0; ks < 4; ++ks) {
            unsigned a[4];
            ldsm_x4_t(a, sptr(&Sksh[(ks*16 + l7 + lhi8)*72 + rt*16 + (lane & 8)]));
            #pragma unroll
            for (int ntp = 0; ntp < 2; ++ntp) {
                unsigned bf[4];
                ldsm_x4_t(bf, sptr(&Vsh[(ks*16 + l15)*72 + ct*32 + ntp*16 + lhi8]));
                mmah(macc[2*ntp],   a, bf);
                mmah(macc[2*ntp+1], a, bf + 2);
            }
        }
    }

    // write partials
    float* mp = g_mpart + (size_t)blockIdx.x * DH*DH;
    int d0 = rt*16 + lr, d1 = d0 + 8;
    #pragma unroll
    for (int nt = 0; nt < 4; ++nt) {
        int c0 = ct*32 + nt*8 + 2*lc;
        *(float2*)&mp[d0*DH + c0] = make_float2(macc[nt][0], macc[nt][1]);
        *(float2*)&mp[d1*DH + c0] = make_float2(macc[nt][2], macc[nt][3]);
    }
    zpart += __shfl_xor_sync(0xffffffffu, zpart, 1);
    zpart += __shfl_xor_sync(0xffffffffu, zpart, 2);
    if (lc == 0) g_zpart[blockIdx.x*DH + dz] = zpart;

    // fused reduction: last CTA of this bh sums the 4 partials
    __threadfence();
    if (tid == 0) slast = atomicInc(&g_cnt[bh], SPLIT - 1);
    __syncthreads();
    if (slast == SPLIT - 1) {
        float beta = 1.f / (1.f + __expf(-beta_lin[0]));
        beta = fminf(fmaxf(beta, 0.9f), 0.999f);
        float* mo = out + A_ELEMS + (size_t)bh*DH*DH;
        for (int e = tid; e < DH*DH; e += 256) {
            float s = beta*Mg[e];
            #pragma unroll
            for (int c = 0; c < SPLIT; ++c)
                s += g_mpart[(size_t)(bh*SPLIT + c)*DH*DH + e];
            mo[e] = s;
        }
        if (tid < DH) {
            float z = 0.f;
            #pragma unroll
            for (int c = 0; c < SPLIT; ++c)
                z += g_zpart[(bh*SPLIT + c)*DH + tid];
            out[A_ELEMS + M_ELEMS + bh*DH + tid] = beta*Z_in[bh*DH + tid] + z;
        }
    }
}

// ---------------------------------------------------------------------------
extern "C" void kernel_launch(void* const* d_in, const int* in_sizes, int n_in,
                              void* d_out, int out_size) {
    const float* x         = (const float*)d_in[0];
    const float* M         = (const float*)d_in[1];
    const float* Z         = (const float*)d_in[2];
    const float* W         = (const float*)d_in[3];
    const float* beta_lin  = (const float*)d_in[4];
    const float* beta_gate = (const float*)d_in[5];
    float* out = (float*)d_out;

    cudaFuncSetAttribute(qkv_gemm, cudaFuncAttributeMaxDynamicSharedMemorySize, QKV_SMEM_BYTES);
    cudaFuncSetAttribute(attn_k, cudaFuncAttributeMaxDynamicSharedMemorySize, ATT_SMEM_BYTES);
    cudaFuncSetAttribute(state_part, cudaFuncAttributeMaxDynamicSharedMemorySize, ST_SMEM_BYTES);

    const int npc = (BB*NQ*DIMK + DIMK*NCOLS)/4;
    preconv<<<(npc + 255)/256, 256>>>(x, W);
    qkv_gemm<<<dim3(NCOLS/128, (BB*NQ)/128), 256, QKV_SMEM_BYTES>>>();
    attn_k<<<dim3(NQ/128, HEADS, BB), 256, ATT_SMEM_BYTES>>>(M, Z, beta_gate, out);
    state_part<<<BB*HEADS*SPLIT, 256, ST_SMEM_BYTES>>>(M, Z, beta_lin, out);
}